// round 1
// baseline (speedup 1.0000x reference)
#include <cuda_runtime.h>
#include <math.h>

#define BB 2
#define QL 2048
#define KLEN 4096
#define H 1024
#define NH 16
#define HD 64
#define SCALE 0.125f
#define LN_EPS 1e-5f

// Scratch (allocation is forbidden; device globals are the sanctioned path)
__device__ float g_Q[BB * QL * H];
__device__ float g_K[BB * KLEN * H];
__device__ float g_V[BB * KLEN * H];
__device__ float g_ctx[BB * QL * H];

// ---------------------------------------------------------------------------
// GEMM: C[M,N] = A[M,K] @ W[K,N] + bias[N]   (all row-major, dims % tile == 0)
// 64x64 tile, BK=16, 256 threads, 4x4 per thread.
// ---------------------------------------------------------------------------
__global__ __launch_bounds__(256) void gemm_bias_kernel(
    const float* __restrict__ A, const float* __restrict__ W,
    const float* __restrict__ bias, float* __restrict__ C,
    int M, int N, int K)
{
    __shared__ float As[16][65];  // [k][m], padded vs bank conflicts
    __shared__ float Ws[16][64];  // [k][n]

    const int tid = threadIdx.x;
    const int tx = tid & 15, ty = tid >> 4;
    const int rowStart = blockIdx.y * 64;
    const int colStart = blockIdx.x * 64;

    float acc[4][4] = {};

    for (int k0 = 0; k0 < K; k0 += 16) {
        #pragma unroll
        for (int e = tid; e < 1024; e += 256) {
            int m = e >> 4, kk = e & 15;
            As[kk][m] = A[(size_t)(rowStart + m) * K + k0 + kk];
        }
        #pragma unroll
        for (int e = tid; e < 1024; e += 256) {
            int kk = e >> 6, n = e & 63;
            Ws[kk][n] = W[(size_t)(k0 + kk) * N + colStart + n];
        }
        __syncthreads();

        #pragma unroll
        for (int kk = 0; kk < 16; kk++) {
            float a[4];
            #pragma unroll
            for (int i = 0; i < 4; i++) a[i] = As[kk][ty * 4 + i];
            float4 wv = *(const float4*)&Ws[kk][tx * 4];
            float w[4] = {wv.x, wv.y, wv.z, wv.w};
            #pragma unroll
            for (int i = 0; i < 4; i++)
                #pragma unroll
                for (int j = 0; j < 4; j++)
                    acc[i][j] = fmaf(a[i], w[j], acc[i][j]);
        }
        __syncthreads();
    }

    #pragma unroll
    for (int j = 0; j < 4; j++) {
        float bj = bias[colStart + tx * 4 + j];
        #pragma unroll
        for (int i = 0; i < 4; i++)
            C[(size_t)(rowStart + ty * 4 + i) * N + colStart + tx * 4 + j] = acc[i][j] + bj;
    }
}

// ---------------------------------------------------------------------------
// Flash attention: one CTA = 64 queries x 1 head. Online softmax over KV.
// KV loop starts at aligned block of answer_start_idx; masked cols -> -inf.
// ---------------------------------------------------------------------------
__global__ __launch_bounds__(256) void attn_kernel(
    const int* __restrict__ ans_ptr, const int* __restrict__ qmask,
    float* __restrict__ ctx)
{
    extern __shared__ float sm[];
    const int R = 68;  // row stride (floats): 272 B, 16B-aligned, conflict-damped
    float* Qs = sm;
    float* Ks = Qs + 64 * R;
    float* Vs = Ks + 64 * R;
    float* Ps = Vs + 64 * R;

    const int tid = threadIdx.x;
    const int tx = tid & 15, ty = tid >> 4;
    const int qb = blockIdx.x * 64;
    const int head = blockIdx.y;
    const int b = blockIdx.z;

    int ans = ans_ptr[0];
    if (ans < 0) ans = 0;
    if (ans > KLEN) ans = KLEN;

    const float* Qg = g_Q + (size_t)b * QL * H + head * HD;
    const float* Kg = g_K + (size_t)b * KLEN * H + head * HD;
    const float* Vg = g_V + (size_t)b * KLEN * H + head * HD;

    // Load Q tile (64 x 64)
    #pragma unroll
    for (int e = tid; e < 64 * 16; e += 256) {
        int m = e >> 4, d4 = (e & 15) * 4;
        *(float4*)&Qs[m * R + d4] = *(const float4*)&Qg[(size_t)(qb + m) * H + d4];
    }

    float mi[4], li[4], o[4][4];
    #pragma unroll
    for (int i = 0; i < 4; i++) {
        mi[i] = -INFINITY; li[i] = 0.f;
        #pragma unroll
        for (int j = 0; j < 4; j++) o[i][j] = 0.f;
    }

    const int kb0 = (ans / 64) * 64;

    for (int kb = kb0; kb < KLEN; kb += 64) {
        __syncthreads();  // protect Ks/Vs/Qs across iterations
        #pragma unroll
        for (int e = tid; e < 64 * 16; e += 256) {
            int m = e >> 4, d4 = (e & 15) * 4;
            *(float4*)&Ks[m * R + d4] = *(const float4*)&Kg[(size_t)(kb + m) * H + d4];
            *(float4*)&Vs[m * R + d4] = *(const float4*)&Vg[(size_t)(kb + m) * H + d4];
        }
        __syncthreads();

        // S = Q K^T (64x64 tile), thread owns rows ty*4.., cols tx*4..
        float s[4][4] = {};
        #pragma unroll 16
        for (int d = 0; d < 64; d++) {
            float a[4], kv[4];
            #pragma unroll
            for (int i = 0; i < 4; i++) a[i] = Qs[(ty * 4 + i) * R + d];
            #pragma unroll
            for (int j = 0; j < 4; j++) kv[j] = Ks[(tx * 4 + j) * R + d];
            #pragma unroll
            for (int i = 0; i < 4; i++)
                #pragma unroll
                for (int j = 0; j < 4; j++)
                    s[i][j] = fmaf(a[i], kv[j], s[i][j]);
        }

        // scale + knowledge mask (k < ans -> -inf). Every block has >=1 valid col.
        #pragma unroll
        for (int j = 0; j < 4; j++) {
            int k = kb + tx * 4 + j;
            bool masked = (k < ans);
            #pragma unroll
            for (int i = 0; i < 4; i++)
                s[i][j] = masked ? -INFINITY : s[i][j] * SCALE;
        }

        // online softmax update
        float mnew[4], alpha[4], rsum[4];
        float p[4][4];
        #pragma unroll
        for (int i = 0; i < 4; i++) {
            float t = fmaxf(fmaxf(s[i][0], s[i][1]), fmaxf(s[i][2], s[i][3]));
            #pragma unroll
            for (int off = 8; off >= 1; off >>= 1)
                t = fmaxf(t, __shfl_xor_sync(0xffffffffu, t, off));
            mnew[i] = fmaxf(mi[i], t);
            alpha[i] = __expf(mi[i] - mnew[i]);  // exp(-inf) == 0 first iter
            float rs = 0.f;
            #pragma unroll
            for (int j = 0; j < 4; j++) {
                p[i][j] = __expf(s[i][j] - mnew[i]);
                rs += p[i][j];
            }
            #pragma unroll
            for (int off = 8; off >= 1; off >>= 1)
                rs += __shfl_xor_sync(0xffffffffu, rs, off);
            rsum[i] = rs;
            li[i] = li[i] * alpha[i] + rsum[i];
            mi[i] = mnew[i];
            #pragma unroll
            for (int j = 0; j < 4; j++) o[i][j] *= alpha[i];
        }

        // stash P tile
        #pragma unroll
        for (int i = 0; i < 4; i++)
            #pragma unroll
            for (int j = 0; j < 4; j++)
                Ps[(ty * 4 + i) * R + tx * 4 + j] = p[i][j];
        __syncthreads();

        // O += P @ V  (thread owns rows ty*4.., HD cols tx*4..)
        #pragma unroll 16
        for (int jj = 0; jj < 64; jj++) {
            float pv[4];
            #pragma unroll
            for (int i = 0; i < 4; i++) pv[i] = Ps[(ty * 4 + i) * R + jj];
            float4 vv = *(const float4*)&Vs[jj * R + tx * 4];
            #pragma unroll
            for (int i = 0; i < 4; i++) {
                o[i][0] = fmaf(pv[i], vv.x, o[i][0]);
                o[i][1] = fmaf(pv[i], vv.y, o[i][1]);
                o[i][2] = fmaf(pv[i], vv.z, o[i][2]);
                o[i][3] = fmaf(pv[i], vv.w, o[i][3]);
            }
        }
    }

    // epilogue: normalize + query-mask semantics (mask==0 -> NaN, matching ref)
    #pragma unroll
    for (int i = 0; i < 4; i++) {
        int q = qb + ty * 4 + i;
        int valid = qmask[b * QL + q];
        float inv = 1.0f / li[i];
        #pragma unroll
        for (int j = 0; j < 4; j++) {
            float val = valid ? o[i][j] * inv : __int_as_float(0x7fc00000);
            ctx[(size_t)(b * QL + q) * H + head * HD + tx * 4 + j] = val;
        }
    }
}

// ---------------------------------------------------------------------------
// Residual + LayerNorm, in place over `out` (which holds ctx @ Wo + bo)
// ---------------------------------------------------------------------------
__global__ __launch_bounds__(256) void ln_kernel(
    const float* __restrict__ x0, float* __restrict__ out,
    const float* __restrict__ w, const float* __restrict__ bvec)
{
    const int row = blockIdx.x;
    const int tid = threadIdx.x;
    const float* xr = x0 + (size_t)row * H;
    float* orow = out + (size_t)row * H;

    float v[4];
    float sum = 0.f, sq = 0.f;
    #pragma unroll
    for (int i = 0; i < 4; i++) {
        int d = tid + i * 256;
        float t = xr[d] + orow[d];
        v[i] = t; sum += t; sq += t * t;
    }
    #pragma unroll
    for (int off = 16; off >= 1; off >>= 1) {
        sum += __shfl_xor_sync(0xffffffffu, sum, off);
        sq  += __shfl_xor_sync(0xffffffffu, sq, off);
    }
    __shared__ float ssum[8], ssq[8];
    int wid = tid >> 5, lane = tid & 31;
    if (lane == 0) { ssum[wid] = sum; ssq[wid] = sq; }
    __syncthreads();
    float tsum = 0.f, tsq = 0.f;
    #pragma unroll
    for (int i = 0; i < 8; i++) { tsum += ssum[i]; tsq += ssq[i]; }
    const float mu = tsum * (1.0f / H);
    const float var = tsq * (1.0f / H) - mu * mu;
    const float inv = rsqrtf(var + LN_EPS);
    #pragma unroll
    for (int i = 0; i < 4; i++) {
        int d = tid + i * 256;
        orow[d] = (v[i] - mu) * inv * w[d] + bvec[d];
    }
}

// ---------------------------------------------------------------------------
extern "C" void kernel_launch(void* const* d_in, const int* in_sizes, int n_in,
                              void* d_out, int out_size)
{
    const float* query     = (const float*)d_in[0];
    const float* knowledge = (const float*)d_in[1];
    const int*   amask     = (const int*)d_in[2];
    const int*   ans       = (const int*)d_in[3];
    const float* Wq = (const float*)d_in[4];
    const float* bq = (const float*)d_in[5];
    const float* Wk = (const float*)d_in[6];
    const float* bk = (const float*)d_in[7];
    const float* Wv = (const float*)d_in[8];
    const float* bv = (const float*)d_in[9];
    const float* Wo = (const float*)d_in[10];
    const float* bo = (const float*)d_in[11];
    const float* lnw = (const float*)d_in[12];
    const float* lnb = (const float*)d_in[13];
    float* out = (float*)d_out;

    float *Qd, *Kd, *Vd, *Cd;
    cudaGetSymbolAddress((void**)&Qd, g_Q);
    cudaGetSymbolAddress((void**)&Kd, g_K);
    cudaGetSymbolAddress((void**)&Vd, g_V);
    cudaGetSymbolAddress((void**)&Cd, g_ctx);

    // Projections
    gemm_bias_kernel<<<dim3(H / 64, (BB * QL) / 64), 256>>>(query,     Wq, bq, Qd, BB * QL,  H, H);
    gemm_bias_kernel<<<dim3(H / 64, (BB * KLEN) / 64), 256>>>(knowledge, Wk, bk, Kd, BB * KLEN, H, H);
    gemm_bias_kernel<<<dim3(H / 64, (BB * KLEN) / 64), 256>>>(knowledge, Wv, bv, Vd, BB * KLEN, H, H);

    // Attention
    size_t smem = 4 * 64 * 68 * sizeof(float);  // 69632 B
    cudaFuncSetAttribute(attn_kernel, cudaFuncAttributeMaxDynamicSharedMemorySize, (int)smem);
    attn_kernel<<<dim3(QL / 64, NH, BB), 256, smem>>>(ans, amask, Cd);

    // Output projection straight into d_out, then fused residual+LN in place
    gemm_bias_kernel<<<dim3(H / 64, (BB * QL) / 64), 256>>>(Cd, Wo, bo, out, BB * QL, H, H);
    ln_kernel<<<BB * QL, 256>>>(query, out, lnw, lnb);
}

// round 3
// speedup vs baseline: 9.0170x; 9.0170x over previous
#include <cuda_runtime.h>
#include <cuda_bf16.h>
#include <cstdint>
#include <stdint.h>
#include <math.h>

#define BB 2
#define QL 2048
#define KLEN 4096
#define H 1024
#define NH 16
#define HD 64
#define SCALE 0.125f
#define LN_EPS 1e-5f

// ---------------- scratch (device globals; allocation forbidden) -----------
__device__ __nv_bfloat16 g_qbf[BB * QL * H];      // query bf16
__device__ __nv_bfloat16 g_kbf[BB * KLEN * H];    // knowledge bf16
__device__ __nv_bfloat16 g_Wq[H * H];
__device__ __nv_bfloat16 g_Wk[H * H];
__device__ __nv_bfloat16 g_Wv[H * H];
__device__ __nv_bfloat16 g_Wo[H * H];
__device__ __nv_bfloat16 g_Q[BB * QL * H];
__device__ __nv_bfloat16 g_K[BB * KLEN * H];
__device__ __nv_bfloat16 g_V[BB * KLEN * H];
__device__ __nv_bfloat16 g_ctx[BB * QL * H];

// ---------------- small helpers -------------------------------------------
__device__ __forceinline__ unsigned smem_u32(const void* p) {
    return (unsigned)__cvta_generic_to_shared(p);
}
__device__ __forceinline__ void ldsm4(unsigned& r0, unsigned& r1, unsigned& r2, unsigned& r3,
                                      unsigned addr) {
    asm volatile("ldmatrix.sync.aligned.m8n8.x4.shared.b16 {%0,%1,%2,%3}, [%4];"
                 : "=r"(r0), "=r"(r1), "=r"(r2), "=r"(r3) : "r"(addr));
}
__device__ __forceinline__ void ldsm4t(unsigned& r0, unsigned& r1, unsigned& r2, unsigned& r3,
                                       unsigned addr) {
    asm volatile("ldmatrix.sync.aligned.m8n8.x4.trans.shared.b16 {%0,%1,%2,%3}, [%4];"
                 : "=r"(r0), "=r"(r1), "=r"(r2), "=r"(r3) : "r"(addr));
}
__device__ __forceinline__ void mma16816(float* c, const unsigned* a, unsigned b0, unsigned b1) {
    asm volatile(
        "mma.sync.aligned.m16n8k16.row.col.f32.bf16.bf16.f32 "
        "{%0,%1,%2,%3}, {%4,%5,%6,%7}, {%8,%9}, {%0,%1,%2,%3};"
        : "+f"(c[0]), "+f"(c[1]), "+f"(c[2]), "+f"(c[3])
        : "r"(a[0]), "r"(a[1]), "r"(a[2]), "r"(a[3]), "r"(b0), "r"(b1));
}
__device__ __forceinline__ unsigned packbf(float lo, float hi) {
    __nv_bfloat162 t = __floats2bfloat162_rn(lo, hi);
    unsigned u;
    memcpy(&u, &t, 4);
    return u;
}

// ---------------- fp32 -> bf16 conversion ----------------------------------
__global__ __launch_bounds__(256) void cvt_kernel(const float* __restrict__ src,
                                                  __nv_bfloat16* __restrict__ dst, int n) {
    int i = (blockIdx.x * 256 + threadIdx.x) * 4;
    if (i < n) {
        float4 v = *(const float4*)(src + i);
        __nv_bfloat162 lo = __floats2bfloat162_rn(v.x, v.y);
        __nv_bfloat162 hi = __floats2bfloat162_rn(v.z, v.w);
        *(__nv_bfloat162*)(dst + i) = lo;
        *(__nv_bfloat162*)(dst + i + 2) = hi;
    }
}

// ---------------------------------------------------------------------------
// Tensor-core GEMM: C[M,1024] = A[M,1024](bf16) @ W[1024,1024](bf16) + bias
// CTA tile 128x128, BK=32, 256 threads = 8 warps (4 row x 2 col),
// warp tile 32x64 = (2 x m16) x (8 x n8). OUT_BF16 selects output dtype.
// ---------------------------------------------------------------------------
template <int OUT_BF16>
__global__ __launch_bounds__(256) void gemm_tc(
    const __nv_bfloat16* __restrict__ A, const __nv_bfloat16* __restrict__ W,
    const float* __restrict__ bias, void* __restrict__ Cout) {
    __shared__ __nv_bfloat16 As[128 * 40];   // stride 40 bf16 = 80B (16B mult, conflict-damped)
    __shared__ __nv_bfloat16 Bs[32 * 136];   // stride 136 bf16 = 272B

    const int tid = threadIdx.x;
    const int lane = tid & 31;
    const int w = tid >> 5;
    const int wm = w >> 1;        // 0..3
    const int wn = w & 1;         // 0..1
    const int bRow = blockIdx.y * 128;
    const int bCol = blockIdx.x * 128;

    float acc[2][8][4];
    #pragma unroll
    for (int i = 0; i < 2; i++)
        #pragma unroll
        for (int j = 0; j < 8; j++)
            #pragma unroll
            for (int q = 0; q < 4; q++) acc[i][j][q] = 0.f;

    // load indices
    const int arow = tid >> 2, acol = (tid & 3) * 8;          // A: rows r and r+64
    const int brow = tid >> 4, bcol = (tid & 15) * 8;          // B: rows r and r+16

    // prologue load of tile 0
    uint4 a0 = *(const uint4*)&A[(size_t)(bRow + arow) * H + acol];
    uint4 a1 = *(const uint4*)&A[(size_t)(bRow + arow + 64) * H + acol];
    uint4 b0 = *(const uint4*)&W[(size_t)brow * H + bCol + bcol];
    uint4 b1 = *(const uint4*)&W[(size_t)(brow + 16) * H + bCol + bcol];

    const unsigned asm_base = smem_u32(As);
    const unsigned bsm_base = smem_u32(Bs);

    for (int k0 = 0; k0 < H; k0 += 32) {
        __syncthreads();
        *(uint4*)&As[arow * 40 + acol] = a0;
        *(uint4*)&As[(arow + 64) * 40 + acol] = a1;
        *(uint4*)&Bs[brow * 136 + bcol] = b0;
        *(uint4*)&Bs[(brow + 16) * 136 + bcol] = b1;
        __syncthreads();

        if (k0 + 32 < H) {  // prefetch next tile (overlaps with compute below)
            a0 = *(const uint4*)&A[(size_t)(bRow + arow) * H + k0 + 32 + acol];
            a1 = *(const uint4*)&A[(size_t)(bRow + arow + 64) * H + k0 + 32 + acol];
            b0 = *(const uint4*)&W[(size_t)(k0 + 32 + brow) * H + bCol + bcol];
            b1 = *(const uint4*)&W[(size_t)(k0 + 32 + brow + 16) * H + bCol + bcol];
        }

        #pragma unroll
        for (int kc = 0; kc < 2; kc++) {
            unsigned af[2][4];
            #pragma unroll
            for (int mt = 0; mt < 2; mt++) {
                unsigned addr = asm_base +
                    ((wm * 32 + mt * 16 + (lane & 15)) * 40 + kc * 16) * 2 + (lane >> 4) * 16;
                ldsm4(af[mt][0], af[mt][1], af[mt][2], af[mt][3], addr);
            }
            #pragma unroll
            for (int np = 0; np < 4; np++) {
                unsigned bf0, bf1, bf2, bf3;
                unsigned addr = bsm_base +
                    ((kc * 16 + (lane & 15)) * 136 + wn * 64 + np * 16) * 2 + (lane >> 4) * 16;
                ldsm4t(bf0, bf1, bf2, bf3, addr);
                #pragma unroll
                for (int mt = 0; mt < 2; mt++) {
                    mma16816(acc[mt][2 * np], af[mt], bf0, bf1);
                    mma16816(acc[mt][2 * np + 1], af[mt], bf2, bf3);
                }
            }
        }
    }

    // epilogue
    #pragma unroll
    for (int mt = 0; mt < 2; mt++) {
        int row = bRow + wm * 32 + mt * 16 + (lane >> 2);
        #pragma unroll
        for (int nt = 0; nt < 8; nt++) {
            int col = bCol + wn * 64 + nt * 8 + (lane & 3) * 2;
            float bb0 = bias[col], bb1 = bias[col + 1];
            float v00 = acc[mt][nt][0] + bb0, v01 = acc[mt][nt][1] + bb1;
            float v10 = acc[mt][nt][2] + bb0, v11 = acc[mt][nt][3] + bb1;
            if (OUT_BF16) {
                __nv_bfloat16* C = (__nv_bfloat16*)Cout;
                *(__nv_bfloat162*)&C[(size_t)row * H + col] = __floats2bfloat162_rn(v00, v01);
                *(__nv_bfloat162*)&C[(size_t)(row + 8) * H + col] = __floats2bfloat162_rn(v10, v11);
            } else {
                float* C = (float*)Cout;
                *(float2*)&C[(size_t)row * H + col] = make_float2(v00, v01);
                *(float2*)&C[(size_t)(row + 8) * H + col] = make_float2(v10, v11);
            }
        }
    }
}

// ---------------------------------------------------------------------------
// Tensor-core flash attention: CTA = 64 queries x 1 head, 4 warps.
// Warp w owns query rows w*16..w*16+15. KV streamed in blocks of 64.
// S = Q K^T via HMMA; online softmax on fragments; P repacked in-register
// as A-fragments for P @ V HMMA. Starts at aligned block of answer_start_idx.
// ---------------------------------------------------------------------------
__global__ __launch_bounds__(128) void attn_tc(
    const int* __restrict__ ans_ptr, const int* __restrict__ qmask,
    const __nv_bfloat16* __restrict__ Qg, const __nv_bfloat16* __restrict__ Kg,
    const __nv_bfloat16* __restrict__ Vg, __nv_bfloat16* __restrict__ ctx) {
    __shared__ __nv_bfloat16 Qs[64 * 72];
    __shared__ __nv_bfloat16 Ks[64 * 72];
    __shared__ __nv_bfloat16 Vs[64 * 72];

    const int tid = threadIdx.x;
    const int lane = tid & 31;
    const int w = tid >> 5;
    const int qb = blockIdx.x * 64;
    const int head = blockIdx.y;
    const int b = blockIdx.z;

    int ans = ans_ptr[0];
    if (ans < 0) ans = 0;
    if (ans > KLEN) ans = KLEN;
    const int kb0 = (ans >> 6) << 6;

    const __nv_bfloat16* Qp = Qg + ((size_t)b * QL + qb) * H + head * HD;
    const __nv_bfloat16* Kp = Kg + ((size_t)b * KLEN) * H + head * HD;
    const __nv_bfloat16* Vp = Vg + ((size_t)b * KLEN) * H + head * HD;

    // load Q tile: 64 rows x 64 cols, 4 x 16B chunks per thread
    #pragma unroll
    for (int i = 0; i < 4; i++) {
        int c = tid + 128 * i;
        *(uint4*)&Qs[(c >> 3) * 72 + (c & 7) * 8] =
            *(const uint4*)&Qp[(size_t)(c >> 3) * H + (c & 7) * 8];
    }
    __syncthreads();

    // hoist Q fragments (warp rows w*16..w*16+15, 4 k16-chunks over d)
    const unsigned qsm = smem_u32(Qs), ksm = smem_u32(Ks), vsm = smem_u32(Vs);
    unsigned qf[4][4];
    #pragma unroll
    for (int kc = 0; kc < 4; kc++) {
        unsigned addr = qsm + ((w * 16 + (lane & 15)) * 72 + kc * 16) * 2 + (lane >> 4) * 16;
        ldsm4(qf[kc][0], qf[kc][1], qf[kc][2], qf[kc][3], addr);
    }

    float o[8][4];
    #pragma unroll
    for (int t = 0; t < 8; t++)
        #pragma unroll
        for (int q = 0; q < 4; q++) o[t][q] = 0.f;
    float m0 = -INFINITY, m1 = -INFINITY, l0 = 0.f, l1 = 0.f;

    // prologue load of first KV block
    uint4 kr[4], vr[4];
    #pragma unroll
    for (int i = 0; i < 4; i++) {
        int c = tid + 128 * i;
        kr[i] = *(const uint4*)&Kp[(size_t)(kb0 + (c >> 3)) * H + (c & 7) * 8];
        vr[i] = *(const uint4*)&Vp[(size_t)(kb0 + (c >> 3)) * H + (c & 7) * 8];
    }

    for (int kb = kb0; kb < KLEN; kb += 64) {
        __syncthreads();
        #pragma unroll
        for (int i = 0; i < 4; i++) {
            int c = tid + 128 * i;
            *(uint4*)&Ks[(c >> 3) * 72 + (c & 7) * 8] = kr[i];
            *(uint4*)&Vs[(c >> 3) * 72 + (c & 7) * 8] = vr[i];
        }
        __syncthreads();

        if (kb + 64 < KLEN) {  // prefetch next block
            #pragma unroll
            for (int i = 0; i < 4; i++) {
                int c = tid + 128 * i;
                kr[i] = *(const uint4*)&Kp[(size_t)(kb + 64 + (c >> 3)) * H + (c & 7) * 8];
                vr[i] = *(const uint4*)&Vp[(size_t)(kb + 64 + (c >> 3)) * H + (c & 7) * 8];
            }
        }

        // S = Q K^T : s[t] covers keys kb + t*8
        float s[8][4];
        #pragma unroll
        for (int t = 0; t < 8; t++)
            #pragma unroll
            for (int q = 0; q < 4; q++) s[t][q] = 0.f;

        #pragma unroll
        for (int kc = 0; kc < 4; kc++) {
            #pragma unroll
            for (int np = 0; np < 4; np++) {
                unsigned bk0, bk1, bk2, bk3;
                unsigned addr = ksm +
                    ((np * 16 + (lane & 7) + ((lane >> 4) << 3)) * 72 +
                     kc * 16 + ((lane >> 3) & 1) * 8) * 2;
                ldsm4(bk0, bk1, bk2, bk3, addr);
                mma16816(s[2 * np], qf[kc], bk0, bk1);
                mma16816(s[2 * np + 1], qf[kc], bk2, bk3);
            }
        }

        // scale + knowledge mask
        #pragma unroll
        for (int t = 0; t < 8; t++)
            #pragma unroll
            for (int q = 0; q < 4; q++) s[t][q] *= SCALE;
        if (kb < ans) {
            #pragma unroll
            for (int t = 0; t < 8; t++) {
                int colb = kb + t * 8 + (lane & 3) * 2;
                #pragma unroll
                for (int q = 0; q < 4; q++)
                    if (colb + (q & 1) < ans) s[t][q] = -INFINITY;
            }
        }

        // online softmax (rows: r = lane/4 and r+8; reduce over lane%4)
        float mx0 = -INFINITY, mx1 = -INFINITY;
        #pragma unroll
        for (int t = 0; t < 8; t++) {
            mx0 = fmaxf(mx0, fmaxf(s[t][0], s[t][1]));
            mx1 = fmaxf(mx1, fmaxf(s[t][2], s[t][3]));
        }
        mx0 = fmaxf(mx0, __shfl_xor_sync(0xffffffffu, mx0, 1));
        mx0 = fmaxf(mx0, __shfl_xor_sync(0xffffffffu, mx0, 2));
        mx1 = fmaxf(mx1, __shfl_xor_sync(0xffffffffu, mx1, 1));
        mx1 = fmaxf(mx1, __shfl_xor_sync(0xffffffffu, mx1, 2));
        float mn0 = fmaxf(m0, mx0), mn1 = fmaxf(m1, mx1);
        float al0 = __expf(m0 - mn0), al1 = __expf(m1 - mn1);
        float sum0 = 0.f, sum1 = 0.f;
        #pragma unroll
        for (int t = 0; t < 8; t++) {
            s[t][0] = __expf(s[t][0] - mn0);
            s[t][1] = __expf(s[t][1] - mn0);
            s[t][2] = __expf(s[t][2] - mn1);
            s[t][3] = __expf(s[t][3] - mn1);
            sum0 += s[t][0] + s[t][1];
            sum1 += s[t][2] + s[t][3];
        }
        sum0 += __shfl_xor_sync(0xffffffffu, sum0, 1);
        sum0 += __shfl_xor_sync(0xffffffffu, sum0, 2);
        sum1 += __shfl_xor_sync(0xffffffffu, sum1, 1);
        sum1 += __shfl_xor_sync(0xffffffffu, sum1, 2);
        l0 = l0 * al0 + sum0;
        l1 = l1 * al1 + sum1;
        m0 = mn0; m1 = mn1;
        #pragma unroll
        for (int t = 0; t < 8; t++) {
            o[t][0] *= al0; o[t][1] *= al0;
            o[t][2] *= al1; o[t][3] *= al1;
        }

        // O += P @ V : repack P fragments from s, B-frags from Vs (trans)
        #pragma unroll
        for (int kk = 0; kk < 4; kk++) {
            unsigned pf[4];
            pf[0] = packbf(s[2 * kk][0], s[2 * kk][1]);
            pf[1] = packbf(s[2 * kk][2], s[2 * kk][3]);
            pf[2] = packbf(s[2 * kk + 1][0], s[2 * kk + 1][1]);
            pf[3] = packbf(s[2 * kk + 1][2], s[2 * kk + 1][3]);
            #pragma unroll
            for (int dp = 0; dp < 4; dp++) {
                unsigned bv0, bv1, bv2, bv3;
                unsigned addr = vsm +
                    ((kk * 16 + (lane & 7) + ((lane >> 3) & 1) * 8) * 72 +
                     dp * 16 + (lane >> 4) * 8) * 2;
                ldsm4t(bv0, bv1, bv2, bv3, addr);
                mma16816(o[2 * dp], pf, bv0, bv1);
                mma16816(o[2 * dp + 1], pf, bv2, bv3);
            }
        }
    }

    // epilogue: normalize, query-mask -> NaN, write bf16 ctx
    const float NaNf = __int_as_float(0x7fc00000);
    float inv0 = 1.f / l0, inv1 = 1.f / l1;
    int r0 = qb + w * 16 + (lane >> 2), r1 = r0 + 8;
    int valid0 = qmask[b * QL + r0], valid1 = qmask[b * QL + r1];
    #pragma unroll
    for (int t = 0; t < 8; t++) {
        int col = t * 8 + (lane & 3) * 2;
        float v00 = valid0 ? o[t][0] * inv0 : NaNf;
        float v01 = valid0 ? o[t][1] * inv0 : NaNf;
        float v10 = valid1 ? o[t][2] * inv1 : NaNf;
        float v11 = valid1 ? o[t][3] * inv1 : NaNf;
        *(__nv_bfloat162*)&ctx[((size_t)b * QL + r0) * H + head * HD + col] =
            __floats2bfloat162_rn(v00, v01);
        *(__nv_bfloat162*)&ctx[((size_t)b * QL + r1) * H + head * HD + col] =
            __floats2bfloat162_rn(v10, v11);
    }
}

// ---------------------------------------------------------------------------
// Residual + LayerNorm (in place over out = ctx@Wo + bo)
// ---------------------------------------------------------------------------
__global__ __launch_bounds__(256) void ln_kernel(
    const float* __restrict__ x0, float* __restrict__ out,
    const float* __restrict__ wv, const float* __restrict__ bvec) {
    const int row = blockIdx.x;
    const int tid = threadIdx.x;
    const float* xr = x0 + (size_t)row * H;
    float* orow = out + (size_t)row * H;

    float v[4];
    float sum = 0.f, sq = 0.f;
    #pragma unroll
    for (int i = 0; i < 4; i++) {
        int d = tid + i * 256;
        float t = xr[d] + orow[d];
        v[i] = t; sum += t; sq += t * t;
    }
    #pragma unroll
    for (int off = 16; off >= 1; off >>= 1) {
        sum += __shfl_xor_sync(0xffffffffu, sum, off);
        sq  += __shfl_xor_sync(0xffffffffu, sq, off);
    }
    __shared__ float ssum[8], ssq[8];
    int wid = tid >> 5, lanei = tid & 31;
    if (lanei == 0) { ssum[wid] = sum; ssq[wid] = sq; }
    __syncthreads();
    float tsum = 0.f, tsq = 0.f;
    #pragma unroll
    for (int i = 0; i < 8; i++) { tsum += ssum[i]; tsq += ssq[i]; }
    const float mu = tsum * (1.0f / H);
    const float var = tsq * (1.0f / H) - mu * mu;
    const float inv = rsqrtf(var + LN_EPS);
    #pragma unroll
    for (int i = 0; i < 4; i++) {
        int d = tid + i * 256;
        orow[d] = (v[i] - mu) * inv * wv[d] + bvec[d];
    }
}

// ---------------------------------------------------------------------------
extern "C" void kernel_launch(void* const* d_in, const int* in_sizes, int n_in,
                              void* d_out, int out_size) {
    const float* query     = (const float*)d_in[0];
    const float* knowledge = (const float*)d_in[1];
    const int*   amask     = (const int*)d_in[2];
    const int*   ans       = (const int*)d_in[3];
    const float* Wq = (const float*)d_in[4];
    const float* bq = (const float*)d_in[5];
    const float* Wk = (const float*)d_in[6];
    const float* bk = (const float*)d_in[7];
    const float* Wv = (const float*)d_in[8];
    const float* bv = (const float*)d_in[9];
    const float* Wo = (const float*)d_in[10];
    const float* bo = (const float*)d_in[11];
    const float* lnw = (const float*)d_in[12];
    const float* lnb = (const float*)d_in[13];
    float* out = (float*)d_out;

    __nv_bfloat16 *qbf, *kbf, *wq, *wk, *wv, *wo, *Qd, *Kd, *Vd, *Cd;
    cudaGetSymbolAddress((void**)&qbf, g_qbf);
    cudaGetSymbolAddress((void**)&kbf, g_kbf);
    cudaGetSymbolAddress((void**)&wq, g_Wq);
    cudaGetSymbolAddress((void**)&wk, g_Wk);
    cudaGetSymbolAddress((void**)&wv, g_Wv);
    cudaGetSymbolAddress((void**)&wo, g_Wo);
    cudaGetSymbolAddress((void**)&Qd, g_Q);
    cudaGetSymbolAddress((void**)&Kd, g_K);
    cudaGetSymbolAddress((void**)&Vd, g_V);
    cudaGetSymbolAddress((void**)&Cd, g_ctx);

    // fp32 -> bf16 conversions
    const int NQ = BB * QL * H, NK = BB * KLEN * H, NW = H * H;
    cvt_kernel<<<NQ / 1024, 256>>>(query, qbf, NQ);
    cvt_kernel<<<NK / 1024, 256>>>(knowledge, kbf, NK);
    cvt_kernel<<<NW / 1024, 256>>>(Wq, wq, NW);
    cvt_kernel<<<NW / 1024, 256>>>(Wk, wk, NW);
    cvt_kernel<<<NW / 1024, 256>>>(Wv, wv, NW);
    cvt_kernel<<<NW / 1024, 256>>>(Wo, wo, NW);

    // projections (tensor-core GEMMs, bf16 out)
    gemm_tc<1><<<dim3(H / 128, (BB * QL) / 128), 256>>>(qbf, wq, bq, Qd);
    gemm_tc<1><<<dim3(H / 128, (BB * KLEN) / 128), 256>>>(kbf, wk, bk, Kd);
    gemm_tc<1><<<dim3(H / 128, (BB * KLEN) / 128), 256>>>(kbf, wv, bv, Vd);

    // attention
    attn_tc<<<dim3(QL / 64, NH, BB), 128>>>(ans, amask, Qd, Kd, Vd, Cd);

    // output projection (fp32 out into d_out), then fused residual + LN
    gemm_tc<0><<<dim3(H / 128, (BB * QL) / 128), 256>>>(Cd, wo, bo, out);
    ln_kernel<<<BB * QL, 256>>>(query, out, lnw, lnb);
}

// round 4
// speedup vs baseline: 9.3335x; 1.0351x over previous
#include <cuda_runtime.h>
#include <cuda_bf16.h>
#include <cstdint>
#include <stdint.h>
#include <math.h>

#define BB 2
#define QL 2048
#define KLEN 4096
#define H 1024
#define NH 16
#define HD 64
#define LN_EPS 1e-5f

// ---------------- scratch (device globals; allocation forbidden) -----------
__device__ __nv_bfloat16 g_qbf[BB * QL * H];
__device__ __nv_bfloat16 g_kbf[BB * KLEN * H];
__device__ __nv_bfloat16 g_Wq[H * H];
__device__ __nv_bfloat16 g_Wk[H * H];
__device__ __nv_bfloat16 g_Wv[H * H];
__device__ __nv_bfloat16 g_Wo[H * H];
__device__ __nv_bfloat16 g_Q[BB * QL * H];      // pre-scaled by 0.125 (exact in bf16)
__device__ __nv_bfloat16 g_K[BB * KLEN * H];
__device__ __nv_bfloat16 g_V[BB * KLEN * H];
__device__ __nv_bfloat16 g_ctx[BB * QL * H];

// ---------------- helpers --------------------------------------------------
__device__ __forceinline__ unsigned smem_u32(const void* p) {
    return (unsigned)__cvta_generic_to_shared(p);
}
__device__ __forceinline__ void ldsm4(unsigned& r0, unsigned& r1, unsigned& r2, unsigned& r3,
                                      unsigned addr) {
    asm volatile("ldmatrix.sync.aligned.m8n8.x4.shared.b16 {%0,%1,%2,%3}, [%4];"
                 : "=r"(r0), "=r"(r1), "=r"(r2), "=r"(r3) : "r"(addr));
}
__device__ __forceinline__ void ldsm4t(unsigned& r0, unsigned& r1, unsigned& r2, unsigned& r3,
                                       unsigned addr) {
    asm volatile("ldmatrix.sync.aligned.m8n8.x4.trans.shared.b16 {%0,%1,%2,%3}, [%4];"
                 : "=r"(r0), "=r"(r1), "=r"(r2), "=r"(r3) : "r"(addr));
}
__device__ __forceinline__ void mma16816(float* c, const unsigned* a, unsigned b0, unsigned b1) {
    asm volatile(
        "mma.sync.aligned.m16n8k16.row.col.f32.bf16.bf16.f32 "
        "{%0,%1,%2,%3}, {%4,%5,%6,%7}, {%8,%9}, {%0,%1,%2,%3};"
        : "+f"(c[0]), "+f"(c[1]), "+f"(c[2]), "+f"(c[3])
        : "r"(a[0]), "r"(a[1]), "r"(a[2]), "r"(a[3]), "r"(b0), "r"(b1));
}
__device__ __forceinline__ unsigned packbf(float lo, float hi) {
    __nv_bfloat162 t = __floats2bfloat162_rn(lo, hi);
    unsigned u;
    memcpy(&u, &t, 4);
    return u;
}
__device__ __forceinline__ void cpasync16(unsigned dst, const void* src) {
    asm volatile("cp.async.cg.shared.global [%0], [%1], 16;" :: "r"(dst), "l"(src));
}
__device__ __forceinline__ void cpcommit() { asm volatile("cp.async.commit_group;"); }
template <int N>
__device__ __forceinline__ void cpwait() { asm volatile("cp.async.wait_group %0;" :: "n"(N)); }

// ---------------- fused fp32 -> bf16 conversion (all 6 tensors) ------------
// segments (1024 elems / block): q:[0,4096) kn:[4096,12288) wq/wk/wv/wo: 1024 each
__global__ __launch_bounds__(256) void cvt_all(
    const float* __restrict__ q, const float* __restrict__ kn,
    const float* __restrict__ wq, const float* __restrict__ wk,
    const float* __restrict__ wv, const float* __restrict__ wo,
    __nv_bfloat16* __restrict__ dq, __nv_bfloat16* __restrict__ dk,
    __nv_bfloat16* __restrict__ dwq, __nv_bfloat16* __restrict__ dwk,
    __nv_bfloat16* __restrict__ dwv, __nv_bfloat16* __restrict__ dwo) {
    int b = blockIdx.x;
    const float* s;
    __nv_bfloat16* d;
    long off;
    if (b < 4096)       { s = q;  d = dq;  off = (long)b * 1024; }
    else if (b < 12288) { s = kn; d = dk;  off = (long)(b - 4096) * 1024; }
    else if (b < 13312) { s = wq; d = dwq; off = (long)(b - 12288) * 1024; }
    else if (b < 14336) { s = wk; d = dwk; off = (long)(b - 13312) * 1024; }
    else if (b < 15360) { s = wv; d = dwv; off = (long)(b - 14336) * 1024; }
    else                { s = wo; d = dwo; off = (long)(b - 15360) * 1024; }
    long i = off + threadIdx.x * 4;
    float4 v = *(const float4*)(s + i);
    *(__nv_bfloat162*)(d + i) = __floats2bfloat162_rn(v.x, v.y);
    *(__nv_bfloat162*)(d + i + 2) = __floats2bfloat162_rn(v.z, v.w);
}

// ---------------------------------------------------------------------------
// Tensor-core GEMM, cp.async 2-stage pipeline. C = alpha*(A@W + bias).
// CTA 128x128, BK=32, 256 threads / 8 warps (4x2), warp tile 32x64.
// ---------------------------------------------------------------------------
#define ASTG (128 * 40)
#define BSTG (32 * 136)
template <int OUT_BF16>
__global__ __launch_bounds__(256) void gemm_tc(
    const __nv_bfloat16* __restrict__ A, const __nv_bfloat16* __restrict__ W,
    const float* __restrict__ bias, void* __restrict__ Cout, float alpha) {
    __shared__ __nv_bfloat16 As[2 * ASTG];
    __shared__ __nv_bfloat16 Bs[2 * BSTG];

    const int tid = threadIdx.x;
    const int lane = tid & 31;
    const int w = tid >> 5;
    const int wm = w >> 1, wn = w & 1;
    const int bRow = blockIdx.y * 128;
    const int bCol = blockIdx.x * 128;

    float acc[2][8][4];
    #pragma unroll
    for (int i = 0; i < 2; i++)
        #pragma unroll
        for (int j = 0; j < 8; j++)
            #pragma unroll
            for (int q = 0; q < 4; q++) acc[i][j][q] = 0.f;

    const int arow = tid >> 2, acol = (tid & 3) * 8;
    const int brow = tid >> 4, bcol = (tid & 15) * 8;
    const unsigned asb = smem_u32(As);
    const unsigned bsb = smem_u32(Bs);

    auto issue = [&](int k0, int st) {
        unsigned ab = asb + st * (ASTG * 2);
        unsigned bb = bsb + st * (BSTG * 2);
        cpasync16(ab + (arow * 40 + acol) * 2, &A[(size_t)(bRow + arow) * H + k0 + acol]);
        cpasync16(ab + ((arow + 64) * 40 + acol) * 2,
                  &A[(size_t)(bRow + arow + 64) * H + k0 + acol]);
        cpasync16(bb + (brow * 136 + bcol) * 2, &W[(size_t)(k0 + brow) * H + bCol + bcol]);
        cpasync16(bb + ((brow + 16) * 136 + bcol) * 2,
                  &W[(size_t)(k0 + brow + 16) * H + bCol + bcol]);
        cpcommit();
    };

    issue(0, 0);

    for (int k0 = 0; k0 < H; k0 += 32) {
        const int cur = (k0 >> 5) & 1;
        cpwait<0>();
        __syncthreads();
        if (k0 + 32 < H) issue(k0 + 32, cur ^ 1);

        const unsigned ab = asb + cur * (ASTG * 2);
        const unsigned bb = bsb + cur * (BSTG * 2);
        #pragma unroll
        for (int kc = 0; kc < 2; kc++) {
            unsigned af[2][4];
            #pragma unroll
            for (int mt = 0; mt < 2; mt++) {
                unsigned addr = ab +
                    ((wm * 32 + mt * 16 + (lane & 15)) * 40 + kc * 16) * 2 + (lane >> 4) * 16;
                ldsm4(af[mt][0], af[mt][1], af[mt][2], af[mt][3], addr);
            }
            #pragma unroll
            for (int np = 0; np < 4; np++) {
                unsigned bf0, bf1, bf2, bf3;
                unsigned addr = bb +
                    ((kc * 16 + (lane & 15)) * 136 + wn * 64 + np * 16) * 2 + (lane >> 4) * 16;
                ldsm4t(bf0, bf1, bf2, bf3, addr);
                #pragma unroll
                for (int mt = 0; mt < 2; mt++) {
                    mma16816(acc[mt][2 * np], af[mt], bf0, bf1);
                    mma16816(acc[mt][2 * np + 1], af[mt], bf2, bf3);
                }
            }
        }
    }

    // epilogue
    #pragma unroll
    for (int mt = 0; mt < 2; mt++) {
        int row = bRow + wm * 32 + mt * 16 + (lane >> 2);
        #pragma unroll
        for (int nt = 0; nt < 8; nt++) {
            int col = bCol + wn * 64 + nt * 8 + (lane & 3) * 2;
            float bb0 = bias[col], bb1 = bias[col + 1];
            float v00 = (acc[mt][nt][0] + bb0) * alpha, v01 = (acc[mt][nt][1] + bb1) * alpha;
            float v10 = (acc[mt][nt][2] + bb0) * alpha, v11 = (acc[mt][nt][3] + bb1) * alpha;
            if (OUT_BF16) {
                __nv_bfloat16* C = (__nv_bfloat16*)Cout;
                *(__nv_bfloat162*)&C[(size_t)row * H + col] = __floats2bfloat162_rn(v00, v01);
                *(__nv_bfloat162*)&C[(size_t)(row + 8) * H + col] = __floats2bfloat162_rn(v10, v11);
            } else {
                float* C = (float*)Cout;
                *(float2*)&C[(size_t)row * H + col] = make_float2(v00, v01);
                *(float2*)&C[(size_t)(row + 8) * H + col] = make_float2(v10, v11);
            }
        }
    }
}

// ---------------------------------------------------------------------------
// Tensor-core flash attention: CTA = 128 queries x 1 head, 8 warps.
// Q pre-scaled by 0.125. KV streamed in 64-blocks via cp.async double buffer.
// ---------------------------------------------------------------------------
#define KVSTG (64 * 72 * 2)   // bytes per KV stage
__global__ __launch_bounds__(256) void attn_tc(
    const int* __restrict__ ans_ptr, const int* __restrict__ qmask,
    const __nv_bfloat16* __restrict__ Qg, const __nv_bfloat16* __restrict__ Kg,
    const __nv_bfloat16* __restrict__ Vg, __nv_bfloat16* __restrict__ ctx) {
    extern __shared__ __nv_bfloat16 smn[];
    __nv_bfloat16* Qs = smn;                    // 128*72
    __nv_bfloat16* Ks0 = Qs + 128 * 72;         // 2 x 64*72
    __nv_bfloat16* Vs0 = Ks0 + 2 * 64 * 72;     // 2 x 64*72

    const int tid = threadIdx.x;
    const int lane = tid & 31;
    const int w = tid >> 5;
    const int qb = blockIdx.x * 128;
    const int head = blockIdx.y;
    const int b = blockIdx.z;

    int ans = ans_ptr[0];
    if (ans < 0) ans = 0;
    if (ans > KLEN) ans = KLEN;
    const int kb0 = (ans >> 6) << 6;

    const __nv_bfloat16* Qp = Qg + ((size_t)b * QL + qb) * H + head * HD;
    const __nv_bfloat16* Kp = Kg + ((size_t)b * KLEN) * H + head * HD;
    const __nv_bfloat16* Vp = Vg + ((size_t)b * KLEN) * H + head * HD;

    const unsigned qsm = smem_u32(Qs);
    const unsigned ksm0 = smem_u32(Ks0);
    const unsigned vsm0 = smem_u32(Vs0);

    auto issueKV = [&](int kb, int st) {
        #pragma unroll
        for (int i = 0; i < 2; i++) {
            int c = tid + 256 * i;
            int row = c >> 3, col = (c & 7) * 8;
            cpasync16(ksm0 + st * KVSTG + (row * 72 + col) * 2,
                      &Kp[(size_t)(kb + row) * H + col]);
            cpasync16(vsm0 + st * KVSTG + (row * 72 + col) * 2,
                      &Vp[(size_t)(kb + row) * H + col]);
        }
        cpcommit();
    };

    issueKV(kb0, 0);

    // Q tile: 128 x 64, plain vector loads
    #pragma unroll
    for (int i = 0; i < 4; i++) {
        int c = tid + 256 * i;
        int row = c >> 3, col = (c & 7) * 8;
        *(uint4*)&Qs[row * 72 + col] = *(const uint4*)&Qp[(size_t)row * H + col];
    }
    __syncthreads();

    // hoist Q fragments (warp rows w*16..w*16+15)
    unsigned qf[4][4];
    #pragma unroll
    for (int kc = 0; kc < 4; kc++) {
        unsigned addr = qsm + ((w * 16 + (lane & 15)) * 72 + kc * 16) * 2 + (lane >> 4) * 16;
        ldsm4(qf[kc][0], qf[kc][1], qf[kc][2], qf[kc][3], addr);
    }

    float o[8][4];
    #pragma unroll
    for (int t = 0; t < 8; t++)
        #pragma unroll
        for (int q = 0; q < 4; q++) o[t][q] = 0.f;
    float m0 = -INFINITY, m1 = -INFINITY, l0 = 0.f, l1 = 0.f;

    for (int kb = kb0; kb < KLEN; kb += 64) {
        const int cur = ((kb - kb0) >> 6) & 1;
        cpwait<0>();
        __syncthreads();
        if (kb + 64 < KLEN) issueKV(kb + 64, cur ^ 1);

        const unsigned ksm = ksm0 + cur * KVSTG;
        const unsigned vsm = vsm0 + cur * KVSTG;

        // S = Q K^T (Q pre-scaled)
        float s[8][4];
        #pragma unroll
        for (int t = 0; t < 8; t++)
            #pragma unroll
            for (int q = 0; q < 4; q++) s[t][q] = 0.f;

        #pragma unroll
        for (int kc = 0; kc < 4; kc++) {
            #pragma unroll
            for (int np = 0; np < 4; np++) {
                unsigned bk0, bk1, bk2, bk3;
                unsigned addr = ksm +
                    ((np * 16 + (lane & 7) + ((lane >> 4) << 3)) * 72 +
                     kc * 16 + ((lane >> 3) & 1) * 8) * 2;
                ldsm4(bk0, bk1, bk2, bk3, addr);
                mma16816(s[2 * np], qf[kc], bk0, bk1);
                mma16816(s[2 * np + 1], qf[kc], bk2, bk3);
            }
        }

        // knowledge mask
        if (kb < ans) {
            #pragma unroll
            for (int t = 0; t < 8; t++) {
                int colb = kb + t * 8 + (lane & 3) * 2;
                #pragma unroll
                for (int q = 0; q < 4; q++)
                    if (colb + (q & 1) < ans) s[t][q] = -INFINITY;
            }
        }

        // online softmax
        float mx0 = -INFINITY, mx1 = -INFINITY;
        #pragma unroll
        for (int t = 0; t < 8; t++) {
            mx0 = fmaxf(mx0, fmaxf(s[t][0], s[t][1]));
            mx1 = fmaxf(mx1, fmaxf(s[t][2], s[t][3]));
        }
        mx0 = fmaxf(mx0, __shfl_xor_sync(0xffffffffu, mx0, 1));
        mx0 = fmaxf(mx0, __shfl_xor_sync(0xffffffffu, mx0, 2));
        mx1 = fmaxf(mx1, __shfl_xor_sync(0xffffffffu, mx1, 1));
        mx1 = fmaxf(mx1, __shfl_xor_sync(0xffffffffu, mx1, 2));
        float mn0 = fmaxf(m0, mx0), mn1 = fmaxf(m1, mx1);
        float al0 = __expf(m0 - mn0), al1 = __expf(m1 - mn1);
        float sum0 = 0.f, sum1 = 0.f;
        #pragma unroll
        for (int t = 0; t < 8; t++) {
            s[t][0] = __expf(s[t][0] - mn0);
            s[t][1] = __expf(s[t][1] - mn0);
            s[t][2] = __expf(s[t][2] - mn1);
            s[t][3] = __expf(s[t][3] - mn1);
            sum0 += s[t][0] + s[t][1];
            sum1 += s[t][2] + s[t][3];
        }
        sum0 += __shfl_xor_sync(0xffffffffu, sum0, 1);
        sum0 += __shfl_xor_sync(0xffffffffu, sum0, 2);
        sum1 += __shfl_xor_sync(0xffffffffu, sum1, 1);
        sum1 += __shfl_xor_sync(0xffffffffu, sum1, 2);
        l0 = l0 * al0 + sum0;
        l1 = l1 * al1 + sum1;
        m0 = mn0; m1 = mn1;
        #pragma unroll
        for (int t = 0; t < 8; t++) {
            o[t][0] *= al0; o[t][1] *= al0;
            o[t][2] *= al1; o[t][3] *= al1;
        }

        // O += P @ V
        #pragma unroll
        for (int kk = 0; kk < 4; kk++) {
            unsigned pf[4];
            pf[0] = packbf(s[2 * kk][0], s[2 * kk][1]);
            pf[1] = packbf(s[2 * kk][2], s[2 * kk][3]);
            pf[2] = packbf(s[2 * kk + 1][0], s[2 * kk + 1][1]);
            pf[3] = packbf(s[2 * kk + 1][2], s[2 * kk + 1][3]);
            #pragma unroll
            for (int dp = 0; dp < 4; dp++) {
                unsigned bv0, bv1, bv2, bv3;
                unsigned addr = vsm +
                    ((kk * 16 + (lane & 7) + ((lane >> 3) & 1) * 8) * 72 +
                     dp * 16 + (lane >> 4) * 8) * 2;
                ldsm4t(bv0, bv1, bv2, bv3, addr);
                mma16816(o[2 * dp], pf, bv0, bv1);
                mma16816(o[2 * dp + 1], pf, bv2, bv3);
            }
        }
    }

    // epilogue
    const float NaNf = __int_as_float(0x7fc00000);
    float inv0 = 1.f / l0, inv1 = 1.f / l1;
    int r0 = qb + w * 16 + (lane >> 2), r1 = r0 + 8;
    int valid0 = qmask[b * QL + r0], valid1 = qmask[b * QL + r1];
    #pragma unroll
    for (int t = 0; t < 8; t++) {
        int col = t * 8 + (lane & 3) * 2;
        float v00 = valid0 ? o[t][0] * inv0 : NaNf;
        float v01 = valid0 ? o[t][1] * inv0 : NaNf;
        float v10 = valid1 ? o[t][2] * inv1 : NaNf;
        float v11 = valid1 ? o[t][3] * inv1 : NaNf;
        *(__nv_bfloat162*)&ctx[((size_t)b * QL + r0) * H + head * HD + col] =
            __floats2bfloat162_rn(v00, v01);
        *(__nv_bfloat162*)&ctx[((size_t)b * QL + r1) * H + head * HD + col] =
            __floats2bfloat162_rn(v10, v11);
    }
}

// ---------------------------------------------------------------------------
// Residual + LayerNorm (in place over out = ctx@Wo + bo)
// ---------------------------------------------------------------------------
__global__ __launch_bounds__(256) void ln_kernel(
    const float* __restrict__ x0, float* __restrict__ out,
    const float* __restrict__ wv, const float* __restrict__ bvec) {
    const int row = blockIdx.x;
    const int tid = threadIdx.x;
    const float* xr = x0 + (size_t)row * H;
    float* orow = out + (size_t)row * H;

    float v[4];
    float sum = 0.f, sq = 0.f;
    #pragma unroll
    for (int i = 0; i < 4; i++) {
        int d = tid + i * 256;
        float t = xr[d] + orow[d];
        v[i] = t; sum += t; sq += t * t;
    }
    #pragma unroll
    for (int off = 16; off >= 1; off >>= 1) {
        sum += __shfl_xor_sync(0xffffffffu, sum, off);
        sq  += __shfl_xor_sync(0xffffffffu, sq, off);
    }
    __shared__ float ssum[8], ssq[8];
    int wid = tid >> 5, lanei = tid & 31;
    if (lanei == 0) { ssum[wid] = sum; ssq[wid] = sq; }
    __syncthreads();
    float tsum = 0.f, tsq = 0.f;
    #pragma unroll
    for (int i = 0; i < 8; i++) { tsum += ssum[i]; tsq += ssq[i]; }
    const float mu = tsum * (1.0f / H);
    const float var = tsq * (1.0f / H) - mu * mu;
    const float inv = rsqrtf(var + LN_EPS);
    #pragma unroll
    for (int i = 0; i < 4; i++) {
        int d = tid + i * 256;
        orow[d] = (v[i] - mu) * inv * wv[d] + bvec[d];
    }
}

// ---------------------------------------------------------------------------
extern "C" void kernel_launch(void* const* d_in, const int* in_sizes, int n_in,
                              void* d_out, int out_size) {
    const float* query     = (const float*)d_in[0];
    const float* knowledge = (const float*)d_in[1];
    const int*   amask     = (const int*)d_in[2];
    const int*   ans       = (const int*)d_in[3];
    const float* Wq = (const float*)d_in[4];
    const float* bq = (const float*)d_in[5];
    const float* Wk = (const float*)d_in[6];
    const float* bk = (const float*)d_in[7];
    const float* Wv = (const float*)d_in[8];
    const float* bv = (const float*)d_in[9];
    const float* Wo = (const float*)d_in[10];
    const float* bo = (const float*)d_in[11];
    const float* lnw = (const float*)d_in[12];
    const float* lnb = (const float*)d_in[13];
    float* out = (float*)d_out;

    __nv_bfloat16 *qbf, *kbf, *wq, *wk, *wv, *wo, *Qd, *Kd, *Vd, *Cd;
    cudaGetSymbolAddress((void**)&qbf, g_qbf);
    cudaGetSymbolAddress((void**)&kbf, g_kbf);
    cudaGetSymbolAddress((void**)&wq, g_Wq);
    cudaGetSymbolAddress((void**)&wk, g_Wk);
    cudaGetSymbolAddress((void**)&wv, g_Wv);
    cudaGetSymbolAddress((void**)&wo, g_Wo);
    cudaGetSymbolAddress((void**)&Qd, g_Q);
    cudaGetSymbolAddress((void**)&Kd, g_K);
    cudaGetSymbolAddress((void**)&Vd, g_V);
    cudaGetSymbolAddress((void**)&Cd, g_ctx);

    // fused conversions: 4096 + 8192 + 4*1024 = 16384 blocks
    cvt_all<<<16384, 256>>>(query, knowledge, Wq, Wk, Wv, Wo,
                            qbf, kbf, wq, wk, wv, wo);

    // projections (Q pre-scaled by 0.125 — exact in bf16)
    gemm_tc<1><<<dim3(H / 128, (BB * QL) / 128), 256>>>(qbf, wq, bq, Qd, 0.125f);
    gemm_tc<1><<<dim3(H / 128, (BB * KLEN) / 128), 256>>>(kbf, wk, bk, Kd, 1.0f);
    gemm_tc<1><<<dim3(H / 128, (BB * KLEN) / 128), 256>>>(kbf, wv, bv, Vd, 1.0f);

    // attention (dynamic smem: Qs + 2xKs + 2xVs = 55296 B)
    const int attn_smem = (128 * 72 + 4 * 64 * 72) * 2;
    cudaFuncSetAttribute(attn_tc, cudaFuncAttributeMaxDynamicSharedMemorySize, attn_smem);
    attn_tc<<<dim3(QL / 128, NH, BB), 256, attn_smem>>>(ans, amask, Qd, Kd, Vd, Cd);

    // output projection into d_out, then fused residual + LN
    gemm_tc<0><<<dim3(H / 128, (BB * QL) / 128), 256>>>(Cd, wo, bo, out, 1.0f);
    ln_kernel<<<BB * QL, 256>>>(query, out, lnw, lnb);
}

// round 6
// speedup vs baseline: 9.6985x; 1.0391x over previous
#include <cuda_runtime.h>
#include <cuda_bf16.h>
#include <cstdint>
#include <stdint.h>
#include <math.h>

#define BB 2
#define QL 2048
#define KLEN 4096
#define H 1024
#define NH 16
#define HD 64
#define LN_EPS 1e-5f

// ---------------- scratch (device globals; allocation forbidden) -----------
__device__ __nv_bfloat16 g_qbf[BB * QL * H];
__device__ __nv_bfloat16 g_kbf[BB * KLEN * H];
__device__ __nv_bfloat16 g_Wq[H * H];
__device__ __nv_bfloat16 g_Wk[H * H];
__device__ __nv_bfloat16 g_Wv[H * H];
__device__ __nv_bfloat16 g_Wo[H * H];
__device__ __nv_bfloat16 g_Q[BB * QL * H];      // pre-scaled by 0.125 (exact in bf16)
__device__ __nv_bfloat16 g_K[BB * KLEN * H];
__device__ __nv_bfloat16 g_V[BB * KLEN * H];
__device__ __nv_bfloat16 g_ctx[BB * QL * H];

// ---------------- helpers --------------------------------------------------
__device__ __forceinline__ unsigned smem_u32(const void* p) {
    return (unsigned)__cvta_generic_to_shared(p);
}
__device__ __forceinline__ void ldsm4(unsigned& r0, unsigned& r1, unsigned& r2, unsigned& r3,
                                      unsigned addr) {
    asm volatile("ldmatrix.sync.aligned.m8n8.x4.shared.b16 {%0,%1,%2,%3}, [%4];"
                 : "=r"(r0), "=r"(r1), "=r"(r2), "=r"(r3) : "r"(addr));
}
__device__ __forceinline__ void ldsm4t(unsigned& r0, unsigned& r1, unsigned& r2, unsigned& r3,
                                       unsigned addr) {
    asm volatile("ldmatrix.sync.aligned.m8n8.x4.trans.shared.b16 {%0,%1,%2,%3}, [%4];"
                 : "=r"(r0), "=r"(r1), "=r"(r2), "=r"(r3) : "r"(addr));
}
__device__ __forceinline__ void mma16816(float* c, const unsigned* a, unsigned b0, unsigned b1) {
    asm volatile(
        "mma.sync.aligned.m16n8k16.row.col.f32.bf16.bf16.f32 "
        "{%0,%1,%2,%3}, {%4,%5,%6,%7}, {%8,%9}, {%0,%1,%2,%3};"
        : "+f"(c[0]), "+f"(c[1]), "+f"(c[2]), "+f"(c[3])
        : "r"(a[0]), "r"(a[1]), "r"(a[2]), "r"(a[3]), "r"(b0), "r"(b1));
}
__device__ __forceinline__ unsigned packbf(float lo, float hi) {
    __nv_bfloat162 t = __floats2bfloat162_rn(lo, hi);
    unsigned u;
    memcpy(&u, &t, 4);
    return u;
}
__device__ __forceinline__ void cpasync16(unsigned dst, const void* src) {
    asm volatile("cp.async.cg.shared.global [%0], [%1], 16;" :: "r"(dst), "l"(src));
}
__device__ __forceinline__ void cpcommit() { asm volatile("cp.async.commit_group;"); }
template <int N>
__device__ __forceinline__ void cpwait() { asm volatile("cp.async.wait_group %0;" :: "n"(N)); }

// ---------------- fused fp32 -> bf16 conversion (all 6 tensors) ------------
__global__ __launch_bounds__(256) void cvt_all(
    const float* __restrict__ q, const float* __restrict__ kn,
    const float* __restrict__ wq, const float* __restrict__ wk,
    const float* __restrict__ wv, const float* __restrict__ wo,
    __nv_bfloat16* __restrict__ dq, __nv_bfloat16* __restrict__ dk,
    __nv_bfloat16* __restrict__ dwq, __nv_bfloat16* __restrict__ dwk,
    __nv_bfloat16* __restrict__ dwv, __nv_bfloat16* __restrict__ dwo) {
    int b = blockIdx.x;
    const float* s;
    __nv_bfloat16* d;
    long off;
    if (b < 4096)       { s = q;  d = dq;  off = (long)b * 1024; }
    else if (b < 12288) { s = kn; d = dk;  off = (long)(b - 4096) * 1024; }
    else if (b < 13312) { s = wq; d = dwq; off = (long)(b - 12288) * 1024; }
    else if (b < 14336) { s = wk; d = dwk; off = (long)(b - 13312) * 1024; }
    else if (b < 15360) { s = wv; d = dwv; off = (long)(b - 14336) * 1024; }
    else                { s = wo; d = dwo; off = (long)(b - 15360) * 1024; }
    long i = off + threadIdx.x * 4;
    float4 v = *(const float4*)(s + i);
    *(__nv_bfloat162*)(d + i) = __floats2bfloat162_rn(v.x, v.y);
    *(__nv_bfloat162*)(d + i + 2) = __floats2bfloat162_rn(v.z, v.w);
}

// ---------------------------------------------------------------------------
// Tensor-core GEMM (HMMA), cp.async 2-stage pipeline. C = alpha*(A@W + bias).
// CTA 128x128, BK=32, 256 threads / 8 warps (4x2), warp tile 32x64.
// (unchanged from the 441us baseline)
// ---------------------------------------------------------------------------
#define ASTG (128 * 40)
#define BSTG (32 * 136)
template <int OUT_BF16>
__global__ __launch_bounds__(256) void gemm_tc(
    const __nv_bfloat16* __restrict__ A, const __nv_bfloat16* __restrict__ W,
    const float* __restrict__ bias, void* __restrict__ Cout, float alpha) {
    __shared__ __nv_bfloat16 As[2 * ASTG];
    __shared__ __nv_bfloat16 Bs[2 * BSTG];

    const int tid = threadIdx.x;
    const int lane = tid & 31;
    const int w = tid >> 5;
    const int wm = w >> 1, wn = w & 1;
    const int bRow = blockIdx.y * 128;
    const int bCol = blockIdx.x * 128;

    float acc[2][8][4];
    #pragma unroll
    for (int i = 0; i < 2; i++)
        #pragma unroll
        for (int j = 0; j < 8; j++)
            #pragma unroll
            for (int q = 0; q < 4; q++) acc[i][j][q] = 0.f;

    const int arow = tid >> 2, acol = (tid & 3) * 8;
    const int brow = tid >> 4, bcol = (tid & 15) * 8;
    const unsigned asb = smem_u32(As);
    const unsigned bsb = smem_u32(Bs);

    auto issue = [&](int k0, int st) {
        unsigned ab = asb + st * (ASTG * 2);
        unsigned bb = bsb + st * (BSTG * 2);
        cpasync16(ab + (arow * 40 + acol) * 2, &A[(size_t)(bRow + arow) * H + k0 + acol]);
        cpasync16(ab + ((arow + 64) * 40 + acol) * 2,
                  &A[(size_t)(bRow + arow + 64) * H + k0 + acol]);
        cpasync16(bb + (brow * 136 + bcol) * 2, &W[(size_t)(k0 + brow) * H + bCol + bcol]);
        cpasync16(bb + ((brow + 16) * 136 + bcol) * 2,
                  &W[(size_t)(k0 + brow + 16) * H + bCol + bcol]);
        cpcommit();
    };

    issue(0, 0);

    for (int k0 = 0; k0 < H; k0 += 32) {
        const int cur = (k0 >> 5) & 1;
        cpwait<0>();
        __syncthreads();
        if (k0 + 32 < H) issue(k0 + 32, cur ^ 1);

        const unsigned ab = asb + cur * (ASTG * 2);
        const unsigned bb = bsb + cur * (BSTG * 2);
        #pragma unroll
        for (int kc = 0; kc < 2; kc++) {
            unsigned af[2][4];
            #pragma unroll
            for (int mt = 0; mt < 2; mt++) {
                unsigned addr = ab +
                    ((wm * 32 + mt * 16 + (lane & 15)) * 40 + kc * 16) * 2 + (lane >> 4) * 16;
                ldsm4(af[mt][0], af[mt][1], af[mt][2], af[mt][3], addr);
            }
            #pragma unroll
            for (int np = 0; np < 4; np++) {
                unsigned bf0, bf1, bf2, bf3;
                unsigned addr = bb +
                    ((kc * 16 + (lane & 15)) * 136 + wn * 64 + np * 16) * 2 + (lane >> 4) * 16;
                ldsm4t(bf0, bf1, bf2, bf3, addr);
                #pragma unroll
                for (int mt = 0; mt < 2; mt++) {
                    mma16816(acc[mt][2 * np], af[mt], bf0, bf1);
                    mma16816(acc[mt][2 * np + 1], af[mt], bf2, bf3);
                }
            }
        }
    }

    // epilogue
    #pragma unroll
    for (int mt = 0; mt < 2; mt++) {
        int row = bRow + wm * 32 + mt * 16 + (lane >> 2);
        #pragma unroll
        for (int nt = 0; nt < 8; nt++) {
            int col = bCol + wn * 64 + nt * 8 + (lane & 3) * 2;
            float bb0 = bias[col], bb1 = bias[col + 1];
            float v00 = (acc[mt][nt][0] + bb0) * alpha, v01 = (acc[mt][nt][1] + bb1) * alpha;
            float v10 = (acc[mt][nt][2] + bb0) * alpha, v11 = (acc[mt][nt][3] + bb1) * alpha;
            if (OUT_BF16) {
                __nv_bfloat16* C = (__nv_bfloat16*)Cout;
                *(__nv_bfloat162*)&C[(size_t)row * H + col] = __floats2bfloat162_rn(v00, v01);
                *(__nv_bfloat162*)&C[(size_t)(row + 8) * H + col] = __floats2bfloat162_rn(v10, v11);
            } else {
                float* C = (float*)Cout;
                *(float2*)&C[(size_t)row * H + col] = make_float2(v00, v01);
                *(float2*)&C[(size_t)(row + 8) * H + col] = make_float2(v10, v11);
            }
        }
    }
}

// ---------------------------------------------------------------------------
// Flash attention v2 (HMMA): CTA = 128 queries x 1 head, 4 warps,
// 32 query rows per warp (2 x m16) -> each K/V fragment feeds 2x the MMAs,
// halving smem ldmatrix traffic per FLOP (smem BW was co-limiting).
// Q pre-scaled by 0.125. KV streamed in 64-blocks via cp.async double buffer.
// ---------------------------------------------------------------------------
#define KVSTG (64 * 72 * 2)
__global__ __launch_bounds__(128) void attn_tc(
    const int* __restrict__ ans_ptr, const int* __restrict__ qmask,
    const __nv_bfloat16* __restrict__ Qg, const __nv_bfloat16* __restrict__ Kg,
    const __nv_bfloat16* __restrict__ Vg, __nv_bfloat16* __restrict__ ctx) {
    extern __shared__ __nv_bfloat16 smn[];
    __nv_bfloat16* Qs = smn;                    // 128*72
    __nv_bfloat16* Ks0 = Qs + 128 * 72;         // 2 x 64*72
    __nv_bfloat16* Vs0 = Ks0 + 2 * 64 * 72;     // 2 x 64*72

    const int tid = threadIdx.x;
    const int lane = tid & 31;
    const int w = tid >> 5;                     // 0..3
    const int qb = blockIdx.x * 128;
    const int head = blockIdx.y;
    const int b = blockIdx.z;

    int ans = ans_ptr[0];
    if (ans < 0) ans = 0;
    if (ans > KLEN) ans = KLEN;
    const int kb0 = (ans >> 6) << 6;

    const __nv_bfloat16* Qp = Qg + ((size_t)b * QL + qb) * H + head * HD;
    const __nv_bfloat16* Kp = Kg + ((size_t)b * KLEN) * H + head * HD;
    const __nv_bfloat16* Vp = Vg + ((size_t)b * KLEN) * H + head * HD;

    const unsigned qsm = smem_u32(Qs);
    const unsigned ksm0 = smem_u32(Ks0);
    const unsigned vsm0 = smem_u32(Vs0);

    auto issueKV = [&](int kb, int st) {
        #pragma unroll
        for (int i = 0; i < 4; i++) {
            int c = tid + 128 * i;              // 0..511
            int row = c >> 3, col = (c & 7) * 8;
            cpasync16(ksm0 + st * KVSTG + (row * 72 + col) * 2,
                      &Kp[(size_t)(kb + row) * H + col]);
            cpasync16(vsm0 + st * KVSTG + (row * 72 + col) * 2,
                      &Vp[(size_t)(kb + row) * H + col]);
        }
        cpcommit();
    };

    issueKV(kb0, 0);

    // Q tile: 128 x 64
    #pragma unroll
    for (int i = 0; i < 8; i++) {
        int c = tid + 128 * i;                  // 0..1023
        int row = c >> 3, col = (c & 7) * 8;
        *(uint4*)&Qs[row * 72 + col] = *(const uint4*)&Qp[(size_t)row * H + col];
    }
    __syncthreads();

    // hoist Q fragments: warp rows w*32 + mt*16 + ...
    unsigned qf[2][4][4];
    #pragma unroll
    for (int mt = 0; mt < 2; mt++)
        #pragma unroll
        for (int kc = 0; kc < 4; kc++) {
            unsigned addr = qsm +
                ((w * 32 + mt * 16 + (lane & 15)) * 72 + kc * 16) * 2 + (lane >> 4) * 16;
            ldsm4(qf[mt][kc][0], qf[mt][kc][1], qf[mt][kc][2], qf[mt][kc][3], addr);
        }

    float o[2][8][4];
    #pragma unroll
    for (int mt = 0; mt < 2; mt++)
        #pragma unroll
        for (int t = 0; t < 8; t++)
            #pragma unroll
            for (int q = 0; q < 4; q++) o[mt][t][q] = 0.f;
    float mrow[2][2], lrow[2][2];
    #pragma unroll
    for (int mt = 0; mt < 2; mt++) {
        mrow[mt][0] = -INFINITY; mrow[mt][1] = -INFINITY;
        lrow[mt][0] = 0.f; lrow[mt][1] = 0.f;
    }

    for (int kb = kb0; kb < KLEN; kb += 64) {
        const int cur = ((kb - kb0) >> 6) & 1;
        cpwait<0>();
        __syncthreads();
        if (kb + 64 < KLEN) issueKV(kb + 64, cur ^ 1);

        const unsigned ksm = ksm0 + cur * KVSTG;
        const unsigned vsm = vsm0 + cur * KVSTG;

        // S = Q K^T (Q pre-scaled); one K fragment serves both m16 sub-tiles
        float s[2][8][4];
        #pragma unroll
        for (int mt = 0; mt < 2; mt++)
            #pragma unroll
            for (int t = 0; t < 8; t++)
                #pragma unroll
                for (int q = 0; q < 4; q++) s[mt][t][q] = 0.f;

        #pragma unroll
        for (int kc = 0; kc < 4; kc++) {
            #pragma unroll
            for (int np = 0; np < 4; np++) {
                unsigned bk0, bk1, bk2, bk3;
                unsigned addr = ksm +
                    ((np * 16 + (lane & 7) + ((lane >> 4) << 3)) * 72 +
                     kc * 16 + ((lane >> 3) & 1) * 8) * 2;
                ldsm4(bk0, bk1, bk2, bk3, addr);
                #pragma unroll
                for (int mt = 0; mt < 2; mt++) {
                    mma16816(s[mt][2 * np], qf[mt][kc], bk0, bk1);
                    mma16816(s[mt][2 * np + 1], qf[mt][kc], bk2, bk3);
                }
            }
        }

        // knowledge mask (col layout independent of mt)
        if (kb < ans) {
            #pragma unroll
            for (int t = 0; t < 8; t++) {
                int colb = kb + t * 8 + (lane & 3) * 2;
                #pragma unroll
                for (int q = 0; q < 4; q++)
                    if (colb + (q & 1) < ans) {
                        s[0][t][q] = -INFINITY;
                        s[1][t][q] = -INFINITY;
                    }
            }
        }

        // online softmax, per m16 sub-tile (rows independent)
        #pragma unroll
        for (int mt = 0; mt < 2; mt++) {
            float mx0 = -INFINITY, mx1 = -INFINITY;
            #pragma unroll
            for (int t = 0; t < 8; t++) {
                mx0 = fmaxf(mx0, fmaxf(s[mt][t][0], s[mt][t][1]));
                mx1 = fmaxf(mx1, fmaxf(s[mt][t][2], s[mt][t][3]));
            }
            mx0 = fmaxf(mx0, __shfl_xor_sync(0xffffffffu, mx0, 1));
            mx0 = fmaxf(mx0, __shfl_xor_sync(0xffffffffu, mx0, 2));
            mx1 = fmaxf(mx1, __shfl_xor_sync(0xffffffffu, mx1, 1));
            mx1 = fmaxf(mx1, __shfl_xor_sync(0xffffffffu, mx1, 2));
            float mn0 = fmaxf(mrow[mt][0], mx0), mn1 = fmaxf(mrow[mt][1], mx1);
            float al0 = __expf(mrow[mt][0] - mn0), al1 = __expf(mrow[mt][1] - mn1);
            float sum0 = 0.f, sum1 = 0.f;
            #pragma unroll
            for (int t = 0; t < 8; t++) {
                s[mt][t][0] = __expf(s[mt][t][0] - mn0);
                s[mt][t][1] = __expf(s[mt][t][1] - mn0);
                s[mt][t][2] = __expf(s[mt][t][2] - mn1);
                s[mt][t][3] = __expf(s[mt][t][3] - mn1);
                sum0 += s[mt][t][0] + s[mt][t][1];
                sum1 += s[mt][t][2] + s[mt][t][3];
            }
            sum0 += __shfl_xor_sync(0xffffffffu, sum0, 1);
            sum0 += __shfl_xor_sync(0xffffffffu, sum0, 2);
            sum1 += __shfl_xor_sync(0xffffffffu, sum1, 1);
            sum1 += __shfl_xor_sync(0xffffffffu, sum1, 2);
            lrow[mt][0] = lrow[mt][0] * al0 + sum0;
            lrow[mt][1] = lrow[mt][1] * al1 + sum1;
            mrow[mt][0] = mn0; mrow[mt][1] = mn1;
            #pragma unroll
            for (int t = 0; t < 8; t++) {
                o[mt][t][0] *= al0; o[mt][t][1] *= al0;
                o[mt][t][2] *= al1; o[mt][t][3] *= al1;
            }
        }

        // O += P @ V ; one V fragment serves both m16 sub-tiles
        #pragma unroll
        for (int kk = 0; kk < 4; kk++) {
            unsigned pf[2][4];
            #pragma unroll
            for (int mt = 0; mt < 2; mt++) {
                pf[mt][0] = packbf(s[mt][2 * kk][0], s[mt][2 * kk][1]);
                pf[mt][1] = packbf(s[mt][2 * kk][2], s[mt][2 * kk][3]);
                pf[mt][2] = packbf(s[mt][2 * kk + 1][0], s[mt][2 * kk + 1][1]);
                pf[mt][3] = packbf(s[mt][2 * kk + 1][2], s[mt][2 * kk + 1][3]);
            }
            #pragma unroll
            for (int dp = 0; dp < 4; dp++) {
                unsigned bv0, bv1, bv2, bv3;
                unsigned addr = vsm +
                    ((kk * 16 + (lane & 7) + ((lane >> 3) & 1) * 8) * 72 +
                     dp * 16 + (lane >> 4) * 8) * 2;
                ldsm4t(bv0, bv1, bv2, bv3, addr);
                #pragma unroll
                for (int mt = 0; mt < 2; mt++) {
                    mma16816(o[mt][2 * dp], pf[mt], bv0, bv1);
                    mma16816(o[mt][2 * dp + 1], pf[mt], bv2, bv3);
                }
            }
        }
    }

    // epilogue: normalize, query-mask -> NaN, write bf16 ctx
    const float NaNf = __int_as_float(0x7fc00000);
    #pragma unroll
    for (int mt = 0; mt < 2; mt++) {
        float inv0 = 1.f / lrow[mt][0], inv1 = 1.f / lrow[mt][1];
        int r0 = qb + w * 32 + mt * 16 + (lane >> 2), r1 = r0 + 8;
        int valid0 = qmask[b * QL + r0], valid1 = qmask[b * QL + r1];
        #pragma unroll
        for (int t = 0; t < 8; t++) {
            int col = t * 8 + (lane & 3) * 2;
            float v00 = valid0 ? o[mt][t][0] * inv0 : NaNf;
            float v01 = valid0 ? o[mt][t][1] * inv0 : NaNf;
            float v10 = valid1 ? o[mt][t][2] * inv1 : NaNf;
            float v11 = valid1 ? o[mt][t][3] * inv1 : NaNf;
            *(__nv_bfloat162*)&ctx[((size_t)b * QL + r0) * H + head * HD + col] =
                __floats2bfloat162_rn(v00, v01);
            *(__nv_bfloat162*)&ctx[((size_t)b * QL + r1) * H + head * HD + col] =
                __floats2bfloat162_rn(v10, v11);
        }
    }
}

// ---------------------------------------------------------------------------
// Residual + LayerNorm (in place over out = ctx@Wo + bo)
// ---------------------------------------------------------------------------
__global__ __launch_bounds__(256) void ln_kernel(
    const float* __restrict__ x0, float* __restrict__ out,
    const float* __restrict__ wv, const float* __restrict__ bvec) {
    const int row = blockIdx.x;
    const int tid = threadIdx.x;
    const float* xr = x0 + (size_t)row * H;
    float* orow = out + (size_t)row * H;

    float v[4];
    float sum = 0.f, sq = 0.f;
    #pragma unroll
    for (int i = 0; i < 4; i++) {
        int d = tid + i * 256;
        float t = xr[d] + orow[d];
        v[i] = t; sum += t; sq += t * t;
    }
    #pragma unroll
    for (int off = 16; off >= 1; off >>= 1) {
        sum += __shfl_xor_sync(0xffffffffu, sum, off);
        sq  += __shfl_xor_sync(0xffffffffu, sq, off);
    }
    __shared__ float ssum[8], ssq[8];
    int wid = tid >> 5, lanei = tid & 31;
    if (lanei == 0) { ssum[wid] = sum; ssq[wid] = sq; }
    __syncthreads();
    float tsum = 0.f, tsq = 0.f;
    #pragma unroll
    for (int i = 0; i < 8; i++) { tsum += ssum[i]; tsq += ssq[i]; }
    const float mu = tsum * (1.0f / H);
    const float var = tsq * (1.0f / H) - mu * mu;
    const float inv = rsqrtf(var + LN_EPS);
    #pragma unroll
    for (int i = 0; i < 4; i++) {
        int d = tid + i * 256;
        orow[d] = (v[i] - mu) * inv * wv[d] + bvec[d];
    }
}

// ---------------------------------------------------------------------------
extern "C" void kernel_launch(void* const* d_in, const int* in_sizes, int n_in,
                              void* d_out, int out_size) {
    const float* query     = (const float*)d_in[0];
    const float* knowledge = (const float*)d_in[1];
    const int*   amask     = (const int*)d_in[2];
    const int*   ans       = (const int*)d_in[3];
    const float* Wq = (const float*)d_in[4];
    const float* bq = (const float*)d_in[5];
    const float* Wk = (const float*)d_in[6];
    const float* bk = (const float*)d_in[7];
    const float* Wv = (const float*)d_in[8];
    const float* bv = (const float*)d_in[9];
    const float* Wo = (const float*)d_in[10];
    const float* bo = (const float*)d_in[11];
    const float* lnw = (const float*)d_in[12];
    const float* lnb = (const float*)d_in[13];
    float* out = (float*)d_out;

    __nv_bfloat16 *qbf, *kbf, *wq, *wk, *wv, *wo, *Qd, *Kd, *Vd, *Cd;
    cudaGetSymbolAddress((void**)&qbf, g_qbf);
    cudaGetSymbolAddress((void**)&kbf, g_kbf);
    cudaGetSymbolAddress((void**)&wq, g_Wq);
    cudaGetSymbolAddress((void**)&wk, g_Wk);
    cudaGetSymbolAddress((void**)&wv, g_Wv);
    cudaGetSymbolAddress((void**)&wo, g_Wo);
    cudaGetSymbolAddress((void**)&Qd, g_Q);
    cudaGetSymbolAddress((void**)&Kd, g_K);
    cudaGetSymbolAddress((void**)&Vd, g_V);
    cudaGetSymbolAddress((void**)&Cd, g_ctx);

    // fused conversions
    cvt_all<<<16384, 256>>>(query, knowledge, Wq, Wk, Wv, Wo,
                            qbf, kbf, wq, wk, wv, wo);

    // projections (Q pre-scaled by 0.125 — exact in bf16)
    gemm_tc<1><<<dim3(H / 128, (BB * QL) / 128), 256>>>(qbf, wq, bq, Qd, 0.125f);
    gemm_tc<1><<<dim3(H / 128, (BB * KLEN) / 128), 256>>>(kbf, wk, bk, Kd, 1.0f);
    gemm_tc<1><<<dim3(H / 128, (BB * KLEN) / 128), 256>>>(kbf, wv, bv, Vd, 1.0f);

    // attention (4 warps, 32 rows/warp; smem: Qs + 2xKs + 2xVs = 55296 B)
    const int attn_smem = (128 * 72 + 4 * 64 * 72) * 2;
    cudaFuncSetAttribute(attn_tc, cudaFuncAttributeMaxDynamicSharedMemorySize, attn_smem);
    attn_tc<<<dim3(QL / 128, NH, BB), 128, attn_smem>>>(ans, amask, Qd, Kd, Vd, Cd);

    // output projection into d_out, then fused residual + LN
    gemm_tc<0><<<dim3(H / 128, (BB * QL) / 128), 256>>>(Cd, wo, bo, out, 1.0f);
    ln_kernel<<<BB * QL, 256>>>(query, out, lnw, lnb);
}

// round 7
// speedup vs baseline: 10.5345x; 1.0862x over previous
#include <cuda_runtime.h>
#include <cuda_bf16.h>
#include <cstdint>
#include <stdint.h>
#include <math.h>

#define BB 2
#define QL 2048
#define KLEN 4096
#define H 1024
#define NH 16
#define HD 64
#define LN_EPS 1e-5f

// ---------------- scratch (device globals; allocation forbidden) -----------
__device__ __nv_bfloat16 g_qbf[BB * QL * H];
__device__ __nv_bfloat16 g_kbf[BB * KLEN * H];
__device__ __nv_bfloat16 g_Wq[H * H];
__device__ __nv_bfloat16 g_Wk[H * H];
__device__ __nv_bfloat16 g_Wv[H * H];
__device__ __nv_bfloat16 g_Wo[H * H];
__device__ __nv_bfloat16 g_Q[BB * QL * H];      // pre-scaled by 0.125*log2e
__device__ __nv_bfloat16 g_K[BB * KLEN * H];
__device__ __nv_bfloat16 g_V[BB * KLEN * H];
__device__ __nv_bfloat16 g_ctx[BB * QL * H];

// ---------------- helpers --------------------------------------------------
__device__ __forceinline__ unsigned smem_u32(const void* p) {
    return (unsigned)__cvta_generic_to_shared(p);
}
__device__ __forceinline__ void ldsm4(unsigned& r0, unsigned& r1, unsigned& r2, unsigned& r3,
                                      unsigned addr) {
    asm volatile("ldmatrix.sync.aligned.m8n8.x4.shared.b16 {%0,%1,%2,%3}, [%4];"
                 : "=r"(r0), "=r"(r1), "=r"(r2), "=r"(r3) : "r"(addr));
}
__device__ __forceinline__ void ldsm4t(unsigned& r0, unsigned& r1, unsigned& r2, unsigned& r3,
                                       unsigned addr) {
    asm volatile("ldmatrix.sync.aligned.m8n8.x4.trans.shared.b16 {%0,%1,%2,%3}, [%4];"
                 : "=r"(r0), "=r"(r1), "=r"(r2), "=r"(r3) : "r"(addr));
}
__device__ __forceinline__ void mma16816(float* c, const unsigned* a, unsigned b0, unsigned b1) {
    asm volatile(
        "mma.sync.aligned.m16n8k16.row.col.f32.bf16.bf16.f32 "
        "{%0,%1,%2,%3}, {%4,%5,%6,%7}, {%8,%9}, {%0,%1,%2,%3};"
        : "+f"(c[0]), "+f"(c[1]), "+f"(c[2]), "+f"(c[3])
        : "r"(a[0]), "r"(a[1]), "r"(a[2]), "r"(a[3]), "r"(b0), "r"(b1));
}
__device__ __forceinline__ unsigned packbf(float lo, float hi) {
    __nv_bfloat162 t = __floats2bfloat162_rn(lo, hi);
    unsigned u;
    memcpy(&u, &t, 4);
    return u;
}
__device__ __forceinline__ unsigned cvtbf2(float hi, float lo) {
    unsigned r;
    asm("cvt.rn.bf16x2.f32 %0, %1, %2;" : "=r"(r) : "f"(hi), "f"(lo));
    return r;
}
__device__ __forceinline__ unsigned ex2b2(unsigned x) {
    unsigned r;
    asm("ex2.approx.ftz.bf16x2 %0, %1;" : "=r"(r) : "r"(x));
    return r;
}
__device__ __forceinline__ float ex2f(float x) {
    float r;
    asm("ex2.approx.f32 %0, %1;" : "=f"(r) : "f"(x));
    return r;
}
__device__ __forceinline__ void cpasync16(unsigned dst, const void* src) {
    asm volatile("cp.async.cg.shared.global [%0], [%1], 16;" :: "r"(dst), "l"(src));
}
__device__ __forceinline__ void cpcommit() { asm volatile("cp.async.commit_group;"); }
template <int N>
__device__ __forceinline__ void cpwait() { asm volatile("cp.async.wait_group %0;" :: "n"(N)); }

// ---------------- fused fp32 -> bf16 conversion (all 6 tensors) ------------
__global__ __launch_bounds__(256) void cvt_all(
    const float* __restrict__ q, const float* __restrict__ kn,
    const float* __restrict__ wq, const float* __restrict__ wk,
    const float* __restrict__ wv, const float* __restrict__ wo,
    __nv_bfloat16* __restrict__ dq, __nv_bfloat16* __restrict__ dk,
    __nv_bfloat16* __restrict__ dwq, __nv_bfloat16* __restrict__ dwk,
    __nv_bfloat16* __restrict__ dwv, __nv_bfloat16* __restrict__ dwo) {
    int b = blockIdx.x;
    const float* s;
    __nv_bfloat16* d;
    long off;
    if (b < 4096)       { s = q;  d = dq;  off = (long)b * 1024; }
    else if (b < 12288) { s = kn; d = dk;  off = (long)(b - 4096) * 1024; }
    else if (b < 13312) { s = wq; d = dwq; off = (long)(b - 12288) * 1024; }
    else if (b < 14336) { s = wk; d = dwk; off = (long)(b - 13312) * 1024; }
    else if (b < 15360) { s = wv; d = dwv; off = (long)(b - 14336) * 1024; }
    else                { s = wo; d = dwo; off = (long)(b - 15360) * 1024; }
    long i = off + threadIdx.x * 4;
    float4 v = *(const float4*)(s + i);
    *(__nv_bfloat162*)(d + i) = __floats2bfloat162_rn(v.x, v.y);
    *(__nv_bfloat162*)(d + i + 2) = __floats2bfloat162_rn(v.z, v.w);
}

// ---------------------------------------------------------------------------
// Tensor-core GEMM (HMMA), BK=64, 2-stage cp.async. C = alpha*(A@W + bias).
// CTA 128x128, 256 threads / 8 warps (4x2), warp tile 32x64. Dynamic smem.
// ---------------------------------------------------------------------------
#define ASTG (128 * 72)           // bf16 elems per A stage
#define BSTG (64 * 136)           // bf16 elems per B stage
#define GSMEM ((2 * ASTG + 2 * BSTG) * 2)
template <int OUT_BF16>
__global__ __launch_bounds__(256) void gemm_tc(
    const __nv_bfloat16* __restrict__ A, const __nv_bfloat16* __restrict__ W,
    const float* __restrict__ bias, void* __restrict__ Cout, float alpha) {
    extern __shared__ __nv_bfloat16 gsm[];
    __nv_bfloat16* As = gsm;                 // 2 stages of 128x72
    __nv_bfloat16* Bs = gsm + 2 * ASTG;      // 2 stages of 64x136

    const int tid = threadIdx.x;
    const int lane = tid & 31;
    const int w = tid >> 5;
    const int wm = w >> 1, wn = w & 1;
    const int bRow = blockIdx.y * 128;
    const int bCol = blockIdx.x * 128;

    float acc[2][8][4];
    #pragma unroll
    for (int i = 0; i < 2; i++)
        #pragma unroll
        for (int j = 0; j < 8; j++)
            #pragma unroll
            for (int q = 0; q < 4; q++) acc[i][j][q] = 0.f;

    const unsigned asb = smem_u32(As);
    const unsigned bsb = smem_u32(Bs);

    auto issue = [&](int k0, int st) {
        unsigned ab = asb + st * (ASTG * 2);
        unsigned bb = bsb + st * (BSTG * 2);
        #pragma unroll
        for (int i = 0; i < 4; i++) {
            int idx = tid + 256 * i;                 // 0..1023
            int arow = idx >> 3, acol = (idx & 7) * 8;
            cpasync16(ab + (arow * 72 + acol) * 2,
                      &A[(size_t)(bRow + arow) * H + k0 + acol]);
            int brow = idx >> 4, bcol = (idx & 15) * 8;
            cpasync16(bb + (brow * 136 + bcol) * 2,
                      &W[(size_t)(k0 + brow) * H + bCol + bcol]);
        }
        cpcommit();
    };

    issue(0, 0);

    for (int k0 = 0; k0 < H; k0 += 64) {
        const int cur = (k0 >> 6) & 1;
        cpwait<0>();
        __syncthreads();
        if (k0 + 64 < H) issue(k0 + 64, cur ^ 1);

        const unsigned ab = asb + cur * (ASTG * 2);
        const unsigned bb = bsb + cur * (BSTG * 2);
        #pragma unroll
        for (int kc = 0; kc < 4; kc++) {
            unsigned af[2][4];
            #pragma unroll
            for (int mt = 0; mt < 2; mt++) {
                unsigned addr = ab +
                    ((wm * 32 + mt * 16 + (lane & 15)) * 72 + kc * 16) * 2 + (lane >> 4) * 16;
                ldsm4(af[mt][0], af[mt][1], af[mt][2], af[mt][3], addr);
            }
            #pragma unroll
            for (int np = 0; np < 4; np++) {
                unsigned bf0, bf1, bf2, bf3;
                unsigned addr = bb +
                    ((kc * 16 + (lane & 15)) * 136 + wn * 64 + np * 16) * 2 + (lane >> 4) * 16;
                ldsm4t(bf0, bf1, bf2, bf3, addr);
                #pragma unroll
                for (int mt = 0; mt < 2; mt++) {
                    mma16816(acc[mt][2 * np], af[mt], bf0, bf1);
                    mma16816(acc[mt][2 * np + 1], af[mt], bf2, bf3);
                }
            }
        }
    }

    // epilogue
    #pragma unroll
    for (int mt = 0; mt < 2; mt++) {
        int row = bRow + wm * 32 + mt * 16 + (lane >> 2);
        #pragma unroll
        for (int nt = 0; nt < 8; nt++) {
            int col = bCol + wn * 64 + nt * 8 + (lane & 3) * 2;
            float bb0 = bias[col], bb1 = bias[col + 1];
            float v00 = (acc[mt][nt][0] + bb0) * alpha, v01 = (acc[mt][nt][1] + bb1) * alpha;
            float v10 = (acc[mt][nt][2] + bb0) * alpha, v11 = (acc[mt][nt][3] + bb1) * alpha;
            if (OUT_BF16) {
                __nv_bfloat16* C = (__nv_bfloat16*)Cout;
                *(__nv_bfloat162*)&C[(size_t)row * H + col] = __floats2bfloat162_rn(v00, v01);
                *(__nv_bfloat162*)&C[(size_t)(row + 8) * H + col] = __floats2bfloat162_rn(v10, v11);
            } else {
                float* C = (float*)Cout;
                *(float2*)&C[(size_t)row * H + col] = make_float2(v00, v01);
                *(float2*)&C[(size_t)(row + 8) * H + col] = make_float2(v10, v11);
            }
        }
    }
}

// ---------------------------------------------------------------------------
// Flash attention v3 (HMMA): CTA = 128 queries x 1 head, 4 warps, 32 rows/warp.
// Scores arrive in log2 domain (Q pre-scaled by 0.125*log2e).
// P computed via bf16x2 ex2 (half the MUFUs, already packed for P@V).
// Row-sum l accumulated as an extra ones-column mma accumulator.
// ---------------------------------------------------------------------------
#define KVSTG (64 * 72 * 2)
__global__ __launch_bounds__(128) void attn_tc(
    const int* __restrict__ ans_ptr, const int* __restrict__ qmask,
    const __nv_bfloat16* __restrict__ Qg, const __nv_bfloat16* __restrict__ Kg,
    const __nv_bfloat16* __restrict__ Vg, __nv_bfloat16* __restrict__ ctx) {
    extern __shared__ __nv_bfloat16 smn[];
    __nv_bfloat16* Qs = smn;
    __nv_bfloat16* Ks0 = Qs + 128 * 72;
    __nv_bfloat16* Vs0 = Ks0 + 2 * 64 * 72;

    const int tid = threadIdx.x;
    const int lane = tid & 31;
    const int w = tid >> 5;
    const int qb = blockIdx.x * 128;
    const int head = blockIdx.y;
    const int b = blockIdx.z;

    int ans = ans_ptr[0];
    if (ans < 0) ans = 0;
    if (ans > KLEN) ans = KLEN;
    const int kb0 = (ans >> 6) << 6;

    const __nv_bfloat16* Qp = Qg + ((size_t)b * QL + qb) * H + head * HD;
    const __nv_bfloat16* Kp = Kg + ((size_t)b * KLEN) * H + head * HD;
    const __nv_bfloat16* Vp = Vg + ((size_t)b * KLEN) * H + head * HD;

    const unsigned qsm = smem_u32(Qs);
    const unsigned ksm0 = smem_u32(Ks0);
    const unsigned vsm0 = smem_u32(Vs0);

    // constant B-fragment for the all-ones column (n8 tile, col0 = 1)
    const unsigned bones = (lane < 4) ? packbf(1.f, 1.f) : 0u;

    auto issueKV = [&](int kb, int st) {
        #pragma unroll
        for (int i = 0; i < 4; i++) {
            int c = tid + 128 * i;
            int row = c >> 3, col = (c & 7) * 8;
            cpasync16(ksm0 + st * KVSTG + (row * 72 + col) * 2,
                      &Kp[(size_t)(kb + row) * H + col]);
            cpasync16(vsm0 + st * KVSTG + (row * 72 + col) * 2,
                      &Vp[(size_t)(kb + row) * H + col]);
        }
        cpcommit();
    };

    issueKV(kb0, 0);

    #pragma unroll
    for (int i = 0; i < 8; i++) {
        int c = tid + 128 * i;
        int row = c >> 3, col = (c & 7) * 8;
        *(uint4*)&Qs[row * 72 + col] = *(const uint4*)&Qp[(size_t)row * H + col];
    }
    __syncthreads();

    unsigned qf[2][4][4];
    #pragma unroll
    for (int mt = 0; mt < 2; mt++)
        #pragma unroll
        for (int kc = 0; kc < 4; kc++) {
            unsigned addr = qsm +
                ((w * 32 + mt * 16 + (lane & 15)) * 72 + kc * 16) * 2 + (lane >> 4) * 16;
            ldsm4(qf[mt][kc][0], qf[mt][kc][1], qf[mt][kc][2], qf[mt][kc][3], addr);
        }

    float o[2][8][4];
    float ol[2][4];
    #pragma unroll
    for (int mt = 0; mt < 2; mt++) {
        #pragma unroll
        for (int t = 0; t < 8; t++)
            #pragma unroll
            for (int q = 0; q < 4; q++) o[mt][t][q] = 0.f;
        #pragma unroll
        for (int q = 0; q < 4; q++) ol[mt][q] = 0.f;
    }
    float mrow[2][2];
    mrow[0][0] = -INFINITY; mrow[0][1] = -INFINITY;
    mrow[1][0] = -INFINITY; mrow[1][1] = -INFINITY;

    for (int kb = kb0; kb < KLEN; kb += 64) {
        const int cur = ((kb - kb0) >> 6) & 1;
        cpwait<0>();
        __syncthreads();
        if (kb + 64 < KLEN) issueKV(kb + 64, cur ^ 1);

        const unsigned ksm = ksm0 + cur * KVSTG;
        const unsigned vsm = vsm0 + cur * KVSTG;

        // S = Q K^T (log2-domain scores)
        float s[2][8][4];
        #pragma unroll
        for (int mt = 0; mt < 2; mt++)
            #pragma unroll
            for (int t = 0; t < 8; t++)
                #pragma unroll
                for (int q = 0; q < 4; q++) s[mt][t][q] = 0.f;

        #pragma unroll
        for (int kc = 0; kc < 4; kc++) {
            #pragma unroll
            for (int np = 0; np < 4; np++) {
                unsigned bk0, bk1, bk2, bk3;
                unsigned addr = ksm +
                    ((np * 16 + (lane & 7) + ((lane >> 4) << 3)) * 72 +
                     kc * 16 + ((lane >> 3) & 1) * 8) * 2;
                ldsm4(bk0, bk1, bk2, bk3, addr);
                #pragma unroll
                for (int mt = 0; mt < 2; mt++) {
                    mma16816(s[mt][2 * np], qf[mt][kc], bk0, bk1);
                    mma16816(s[mt][2 * np + 1], qf[mt][kc], bk2, bk3);
                }
            }
        }

        if (kb < ans) {
            #pragma unroll
            for (int t = 0; t < 8; t++) {
                int colb = kb + t * 8 + (lane & 3) * 2;
                #pragma unroll
                for (int q = 0; q < 4; q++)
                    if (colb + (q & 1) < ans) {
                        s[0][t][q] = -INFINITY;
                        s[1][t][q] = -INFINITY;
                    }
            }
        }

        // online softmax in log2 domain; P in bf16x2 via ex2
        unsigned p01[2][8], p23[2][8];
        #pragma unroll
        for (int mt = 0; mt < 2; mt++) {
            float mx0 = -INFINITY, mx1 = -INFINITY;
            #pragma unroll
            for (int t = 0; t < 8; t++) {
                mx0 = fmaxf(mx0, fmaxf(s[mt][t][0], s[mt][t][1]));
                mx1 = fmaxf(mx1, fmaxf(s[mt][t][2], s[mt][t][3]));
            }
            mx0 = fmaxf(mx0, __shfl_xor_sync(0xffffffffu, mx0, 1));
            mx0 = fmaxf(mx0, __shfl_xor_sync(0xffffffffu, mx0, 2));
            mx1 = fmaxf(mx1, __shfl_xor_sync(0xffffffffu, mx1, 1));
            mx1 = fmaxf(mx1, __shfl_xor_sync(0xffffffffu, mx1, 2));
            float mn0 = fmaxf(mrow[mt][0], mx0), mn1 = fmaxf(mrow[mt][1], mx1);
            float al0 = ex2f(mrow[mt][0] - mn0), al1 = ex2f(mrow[mt][1] - mn1);
            mrow[mt][0] = mn0; mrow[mt][1] = mn1;
            if (al0 != 1.f || al1 != 1.f) {   // rescale only when max moved
                #pragma unroll
                for (int t = 0; t < 8; t++) {
                    o[mt][t][0] *= al0; o[mt][t][1] *= al0;
                    o[mt][t][2] *= al1; o[mt][t][3] *= al1;
                }
                ol[mt][0] *= al0; ol[mt][1] *= al0;
                ol[mt][2] *= al1; ol[mt][3] *= al1;
            }
            #pragma unroll
            for (int t = 0; t < 8; t++) {
                float d0 = s[mt][t][0] - mn0, d1 = s[mt][t][1] - mn0;
                float d2 = s[mt][t][2] - mn1, d3 = s[mt][t][3] - mn1;
                p01[mt][t] = ex2b2(cvtbf2(d1, d0));
                p23[mt][t] = ex2b2(cvtbf2(d3, d2));
            }
        }

        // O += P @ V  (+ ones column accumulates l)
        #pragma unroll
        for (int kk = 0; kk < 4; kk++) {
            unsigned pf[2][4];
            #pragma unroll
            for (int mt = 0; mt < 2; mt++) {
                pf[mt][0] = p01[mt][2 * kk];
                pf[mt][1] = p23[mt][2 * kk];
                pf[mt][2] = p01[mt][2 * kk + 1];
                pf[mt][3] = p23[mt][2 * kk + 1];
            }
            #pragma unroll
            for (int dp = 0; dp < 4; dp++) {
                unsigned bv0, bv1, bv2, bv3;
                unsigned addr = vsm +
                    ((kk * 16 + (lane & 7) + ((lane >> 3) & 1) * 8) * 72 +
                     dp * 16 + (lane >> 4) * 8) * 2;
                ldsm4t(bv0, bv1, bv2, bv3, addr);
                #pragma unroll
                for (int mt = 0; mt < 2; mt++) {
                    mma16816(o[mt][2 * dp], pf[mt], bv0, bv1);
                    mma16816(o[mt][2 * dp + 1], pf[mt], bv2, bv3);
                }
            }
            #pragma unroll
            for (int mt = 0; mt < 2; mt++)
                mma16816(ol[mt], pf[mt], bones, bones);
        }
    }

    // epilogue: fetch l from quad-base lane, normalize, qmask -> NaN
    const float NaNf = __int_as_float(0x7fc00000);
    #pragma unroll
    for (int mt = 0; mt < 2; mt++) {
        float l0 = __shfl_sync(0xffffffffu, ol[mt][0], lane & ~3);
        float l1 = __shfl_sync(0xffffffffu, ol[mt][2], lane & ~3);
        float inv0 = 1.f / l0, inv1 = 1.f / l1;
        int r0 = qb + w * 32 + mt * 16 + (lane >> 2), r1 = r0 + 8;
        int valid0 = qmask[b * QL + r0], valid1 = qmask[b * QL + r1];
        #pragma unroll
        for (int t = 0; t < 8; t++) {
            int col = t * 8 + (lane & 3) * 2;
            float v00 = valid0 ? o[mt][t][0] * inv0 : NaNf;
            float v01 = valid0 ? o[mt][t][1] * inv0 : NaNf;
            float v10 = valid1 ? o[mt][t][2] * inv1 : NaNf;
            float v11 = valid1 ? o[mt][t][3] * inv1 : NaNf;
            *(__nv_bfloat162*)&ctx[((size_t)b * QL + r0) * H + head * HD + col] =
                __floats2bfloat162_rn(v00, v01);
            *(__nv_bfloat162*)&ctx[((size_t)b * QL + r1) * H + head * HD + col] =
                __floats2bfloat162_rn(v10, v11);
        }
    }
}

// ---------------------------------------------------------------------------
// Residual + LayerNorm (in place over out = ctx@Wo + bo)
// ---------------------------------------------------------------------------
__global__ __launch_bounds__(256) void ln_kernel(
    const float* __restrict__ x0, float* __restrict__ out,
    const float* __restrict__ wv, const float* __restrict__ bvec) {
    const int row = blockIdx.x;
    const int tid = threadIdx.x;
    const float* xr = x0 + (size_t)row * H;
    float* orow = out + (size_t)row * H;

    float v[4];
    float sum = 0.f, sq = 0.f;
    #pragma unroll
    for (int i = 0; i < 4; i++) {
        int d = tid + i * 256;
        float t = xr[d] + orow[d];
        v[i] = t; sum += t; sq += t * t;
    }
    #pragma unroll
    for (int off = 16; off >= 1; off >>= 1) {
        sum += __shfl_xor_sync(0xffffffffu, sum, off);
        sq  += __shfl_xor_sync(0xffffffffu, sq, off);
    }
    __shared__ float ssum[8], ssq[8];
    int wid = tid >> 5, lanei = tid & 31;
    if (lanei == 0) { ssum[wid] = sum; ssq[wid] = sq; }
    __syncthreads();
    float tsum = 0.f, tsq = 0.f;
    #pragma unroll
    for (int i = 0; i < 8; i++) { tsum += ssum[i]; tsq += ssq[i]; }
    const float mu = tsum * (1.0f / H);
    const float var = tsq * (1.0f / H) - mu * mu;
    const float inv = rsqrtf(var + LN_EPS);
    #pragma unroll
    for (int i = 0; i < 4; i++) {
        int d = tid + i * 256;
        orow[d] = (v[i] - mu) * inv * wv[d] + bvec[d];
    }
}

// ---------------------------------------------------------------------------
extern "C" void kernel_launch(void* const* d_in, const int* in_sizes, int n_in,
                              void* d_out, int out_size) {
    const float* query     = (const float*)d_in[0];
    const float* knowledge = (const float*)d_in[1];
    const int*   amask     = (const int*)d_in[2];
    const int*   ans       = (const int*)d_in[3];
    const float* Wq = (const float*)d_in[4];
    const float* bq = (const float*)d_in[5];
    const float* Wk = (const float*)d_in[6];
    const float* bk = (const float*)d_in[7];
    const float* Wv = (const float*)d_in[8];
    const float* bv = (const float*)d_in[9];
    const float* Wo = (const float*)d_in[10];
    const float* bo = (const float*)d_in[11];
    const float* lnw = (const float*)d_in[12];
    const float* lnb = (const float*)d_in[13];
    float* out = (float*)d_out;

    __nv_bfloat16 *qbf, *kbf, *wq, *wk, *wv, *wo, *Qd, *Kd, *Vd, *Cd;
    cudaGetSymbolAddress((void**)&qbf, g_qbf);
    cudaGetSymbolAddress((void**)&kbf, g_kbf);
    cudaGetSymbolAddress((void**)&wq, g_Wq);
    cudaGetSymbolAddress((void**)&wk, g_Wk);
    cudaGetSymbolAddress((void**)&wv, g_Wv);
    cudaGetSymbolAddress((void**)&wo, g_Wo);
    cudaGetSymbolAddress((void**)&Qd, g_Q);
    cudaGetSymbolAddress((void**)&Kd, g_K);
    cudaGetSymbolAddress((void**)&Vd, g_V);
    cudaGetSymbolAddress((void**)&Cd, g_ctx);

    // fused conversions
    cvt_all<<<16384, 256>>>(query, knowledge, Wq, Wk, Wv, Wo,
                            qbf, kbf, wq, wk, wv, wo);

    // projections; Q pre-scaled by 0.125*log2e (scores in log2 domain)
    const float QSCALE = 0.125f * 1.4426950408889634f;
    cudaFuncSetAttribute(gemm_tc<1>, cudaFuncAttributeMaxDynamicSharedMemorySize, GSMEM);
    cudaFuncSetAttribute(gemm_tc<0>, cudaFuncAttributeMaxDynamicSharedMemorySize, GSMEM);
    gemm_tc<1><<<dim3(H / 128, (BB * QL) / 128), 256, GSMEM>>>(qbf, wq, bq, Qd, QSCALE);
    gemm_tc<1><<<dim3(H / 128, (BB * KLEN) / 128), 256, GSMEM>>>(kbf, wk, bk, Kd, 1.0f);
    gemm_tc<1><<<dim3(H / 128, (BB * KLEN) / 128), 256, GSMEM>>>(kbf, wv, bv, Vd, 1.0f);

    // attention
    const int attn_smem = (128 * 72 + 4 * 64 * 72) * 2;
    cudaFuncSetAttribute(attn_tc, cudaFuncAttributeMaxDynamicSharedMemorySize, attn_smem);
    attn_tc<<<dim3(QL / 128, NH, BB), 128, attn_smem>>>(ans, amask, Qd, Kd, Vd, Cd);

    // output projection into d_out, then fused residual + LN
    gemm_tc<0><<<dim3(H / 128, (BB * QL) / 128), 256, GSMEM>>>(Cd, wo, bo, out, 1.0f);
    ln_kernel<<<BB * QL, 256>>>(query, out, lnw, lnb);
}